// round 2
// baseline (speedup 1.0000x reference)
#include <cuda_runtime.h>
#include <cuda_bf16.h>

// Sim2: temporal cost-volume + softmax + 1x1convs on a 3-level pyramid.
// All fp32. Stages:
//   k_sim      : partial cost volume L[cc][b,t,s,px] (smem-tiled, float4-over-c)
//   k_softconv1: reduce chunks + softmax(81) + conv1(243->4) + BN + SiLU
//   k_resize   : bilinear align_corners upsample of the 4-ch sim feature
//   k_conv2    : per-level (C+4)->C 1x1 conv + BN + SiLU  (SIMT GEMM 64x64x16)

#define B_   4
#define C2   512
#define HW2  400
#define NS_  81
#define NCHUNK 8
#define CCH  64

__device__ float g_Lpart[NCHUNK * 12 * NS_ * HW2];   // 12.4 MB scratch
__device__ float g_simf[B_ * 4 * HW2];
__device__ float g_pr0[B_ * 4 * 6400];
__device__ float g_pr1[B_ * 4 * 1600];

// ---------------------------------------------------------------------------
// Kernel 1: cost volume partials. grid = (NCHUNK, B*3), 512 threads.
// smem: curS[16][400] float4 (c-fastest), pastS[16][400] float4 -> 204.8 KB
// ---------------------------------------------------------------------------
__global__ __launch_bounds__(512) void k_sim(const float* __restrict__ f2)
{
    int cc = blockIdx.x;            // channel chunk 0..7
    int bt = blockIdx.y;            // 0..11  (b*3 + t)
    int b = bt / 3, t = bt - 3 * b;

    extern __shared__ float4 sh4[];
    float4* curS  = sh4;            // [16][400]
    float4* pastS = sh4 + 16 * HW2; // [16][400]

    const float* curG  = f2 + ((size_t)(b * 4 + 3) * C2 + cc * CCH) * HW2;
    const float* pastG = f2 + ((size_t)(b * 4 + t) * C2 + cc * CCH) * HW2;

    for (int idx = threadIdx.x; idx < 16 * HW2; idx += 512) {
        int c4 = idx / HW2, px = idx - c4 * HW2;
        int g = c4 * 4 * HW2 + px;
        curS[idx]  = make_float4(curG[g],  curG[g + HW2],  curG[g + 2 * HW2],  curG[g + 3 * HW2]);
        pastS[idx] = make_float4(pastG[g], pastG[g + HW2], pastG[g + 2 * HW2], pastG[g + 3 * HW2]);
    }
    __syncthreads();

    float* Lp = g_Lpart + ((size_t)cc * 12 + bt) * (NS_ * HW2);

    for (int i = threadIdx.x; i < NS_ * HW2; i += 512) {
        int s  = i / HW2, px = i - s * HW2;
        int y  = px / 20, x  = px - y * 20;
        int yy = y + s / 9 - 4;
        int xx = x + s % 9 - 4;

        float acc = 0.f;
        const float4* pp = pastS + px;
        if ((unsigned)yy < 20u && (unsigned)xx < 20u) {
            const float4* cp = curS + yy * 20 + xx;
#pragma unroll
            for (int c = 0; c < 16; c++) {
                float4 a = cp[c * HW2];
                float4 p = pp[c * HW2];
                acc -= fabsf(a.x - p.x); acc -= fabsf(a.y - p.y);
                acc -= fabsf(a.z - p.z); acc -= fabsf(a.w - p.w);
            }
        } else {
#pragma unroll
            for (int c = 0; c < 16; c++) {
                float4 p = pp[c * HW2];
                acc -= fabsf(p.x); acc -= fabsf(p.y);
                acc -= fabsf(p.z); acc -= fabsf(p.w);
            }
        }
        Lp[i] = acc;
    }
}

// ---------------------------------------------------------------------------
// Kernel 2: reduce 8 chunks, softmax over 81 displacements (per t),
// conv1 (3*81 -> 4) + BN + SiLU. grid = (4, B), 512 threads.
// threads = 128 px lanes x 4 groups. smem: Ls[243][128] + opart[12][128]
// ---------------------------------------------------------------------------
__global__ __launch_bounds__(512) void k_softconv1(
    const float* __restrict__ w1,
    const float* __restrict__ g1, const float* __restrict__ b1,
    const float* __restrict__ m1, const float* __restrict__ v1)
{
    int b    = blockIdx.y;
    int lane = threadIdx.x & 127;
    int grp  = threadIdx.x >> 7;
    int px   = blockIdx.x * 128 + lane;
    bool act = px < HW2;

    extern __shared__ float Ls[];           // [243][128]
    float* opart = Ls + 243 * 128;          // [12][128]

    const float* base = g_Lpart + (size_t)(b * 3) * NS_ * HW2;

    for (int ts = grp; ts < 243; ts += 4) {
        float vsum = 0.f;
        if (act) {
            size_t off = (size_t)ts * HW2 + px;
#pragma unroll
            for (int cc = 0; cc < NCHUNK; cc++)
                vsum += base[(size_t)cc * (12 * NS_ * HW2) + off];
        }
        Ls[ts * 128 + lane] = vsum;
    }
    __syncthreads();

    if (grp < 3) {
        int t = grp;
        float mx = -1e30f;
        for (int s = 0; s < 81; s++)
            mx = fmaxf(mx, Ls[(t * 81 + s) * 128 + lane]);
        float Z = 0.f;
        for (int s = 0; s < 81; s++)
            Z += __expf(Ls[(t * 81 + s) * 128 + lane] - mx);
        float rz = 1.f / Z;
        float o0 = 0, o1 = 0, o2 = 0, o3 = 0;
        for (int s = 0; s < 81; s++) {
            int k = t * 81 + s;
            float p = __expf(Ls[k * 128 + lane] - mx) * rz;
            o0 += w1[k] * p;       o1 += w1[243 + k] * p;
            o2 += w1[486 + k] * p; o3 += w1[729 + k] * p;
        }
        opart[(t * 4 + 0) * 128 + lane] = o0;
        opart[(t * 4 + 1) * 128 + lane] = o1;
        opart[(t * 4 + 2) * 128 + lane] = o2;
        opart[(t * 4 + 3) * 128 + lane] = o3;
    }
    __syncthreads();

    if (grp == 3 && act) {
#pragma unroll
        for (int oc = 0; oc < 4; oc++) {
            float o = opart[oc * 128 + lane] + opart[(4 + oc) * 128 + lane]
                    + opart[(8 + oc) * 128 + lane];
            float sc = g1[oc] * rsqrtf(v1[oc] + 1e-3f);
            float yv = (o - m1[oc]) * sc + b1[oc];
            g_simf[((size_t)b * 4 + oc) * HW2 + px] = yv / (1.f + __expf(-yv));
        }
    }
}

// ---------------------------------------------------------------------------
// Kernel 3: bilinear resize 20x20 -> Ho x Wo, align_corners=True
// ---------------------------------------------------------------------------
__global__ void k_resize(float* __restrict__ dst, int Ho, int Wo)
{
    int idx = blockIdx.x * 256 + threadIdx.x;
    int total = B_ * 4 * Ho * Wo;
    if (idx >= total) return;
    int xo = idx % Wo;
    int r  = idx / Wo;
    int yo = r % Ho;
    int bc = r / Ho;                         // b*4 + ch

    float cy = yo * (19.f / (float)(Ho - 1));
    float cx = xo * (19.f / (float)(Wo - 1));
    int y0 = (int)floorf(cy), x0 = (int)floorf(cx);
    int y1 = min(y0 + 1, 19), x1 = min(x0 + 1, 19);
    float wy = cy - (float)y0, wx = cx - (float)x0;

    const float* sp = g_simf + (size_t)bc * HW2;
    float v = (1.f - wy) * ((1.f - wx) * sp[y0 * 20 + x0] + wx * sp[y0 * 20 + x1])
            +         wy * ((1.f - wx) * sp[y1 * 20 + x0] + wx * sp[y1 * 20 + x1]);
    dst[idx] = v;
}

// ---------------------------------------------------------------------------
// Kernel 4: per-level 1x1 conv (C+4 -> C) + BN + SiLU.
// SIMT GEMM: block tile 64(o) x 64(px), K-chunk 16, 256 threads, 4x4 microtile.
// grid = (ceil(HW/64), C/64, B)
// ---------------------------------------------------------------------------
__global__ __launch_bounds__(256) void k_conv2(
    const float* __restrict__ feat,   // [B][4][C][HW], frame 3 used
    const float* __restrict__ pr,     // [B][4][HW]
    const float* __restrict__ w2,     // [C][C+4]
    const float* __restrict__ gg, const float* __restrict__ bb,
    const float* __restrict__ mm, const float* __restrict__ vv,
    float* __restrict__ out,          // [B][C][HW]
    int C, int HW)
{
    __shared__ float wsT[16][68];     // [k][o]
    __shared__ float xs[16][68];      // [k][px]

    int b     = blockIdx.z;
    int otile = blockIdx.y * 64;
    int ptile = blockIdx.x * 64;
    int K     = C + 4;

    const float* xbase = feat + (size_t)(b * 4 + 3) * C * HW;
    const float* prb   = pr + (size_t)b * 4 * HW;

    int tx = threadIdx.x & 15;
    int ty = threadIdx.x >> 4;

    float acc[4][4] = {};

    for (int k0 = 0; k0 < K; k0 += 16) {
        for (int i = threadIdx.x; i < 1024; i += 256) {
            int k = i & 15, o = i >> 4;
            int kk = k0 + k;
            wsT[k][o] = (kk < K) ? w2[(size_t)(otile + o) * K + kk] : 0.f;
        }
        for (int i = threadIdx.x; i < 1024; i += 256) {
            int px = i & 63, k = i >> 6;
            int kk = k0 + k, pp = ptile + px;
            float val = 0.f;
            if (kk < K && pp < HW)
                val = (kk < C) ? xbase[(size_t)kk * HW + pp]
                               : prb[(size_t)(kk - C) * HW + pp];
            xs[k][px] = val;
        }
        __syncthreads();
#pragma unroll
        for (int k = 0; k < 16; k++) {
            float4 a  = *(const float4*)&wsT[k][ty * 4];
            float4 xv = *(const float4*)&xs[k][tx * 4];
            acc[0][0] += a.x * xv.x; acc[0][1] += a.x * xv.y; acc[0][2] += a.x * xv.z; acc[0][3] += a.x * xv.w;
            acc[1][0] += a.y * xv.x; acc[1][1] += a.y * xv.y; acc[1][2] += a.y * xv.z; acc[1][3] += a.y * xv.w;
            acc[2][0] += a.z * xv.x; acc[2][1] += a.z * xv.y; acc[2][2] += a.z * xv.z; acc[2][3] += a.z * xv.w;
            acc[3][0] += a.w * xv.x; acc[3][1] += a.w * xv.y; acc[3][2] += a.w * xv.z; acc[3][3] += a.w * xv.w;
        }
        __syncthreads();
    }

#pragma unroll
    for (int i = 0; i < 4; i++) {
        int oo = otile + ty * 4 + i;          // C is a multiple of 64 -> always valid
        float sc = gg[oo] * rsqrtf(vv[oo] + 1e-3f);
        float sh = bb[oo] - mm[oo] * sc;
        int pp0 = ptile + tx * 4;
        float4 r;
        float* rp = &r.x;
#pragma unroll
        for (int j = 0; j < 4; j++) {
            float yv = acc[i][j] * sc + sh;
            rp[j] = yv / (1.f + __expf(-yv));
        }
        float* ob = out + (size_t)(b * C + oo) * HW;
        if (pp0 + 3 < HW) {
            *(float4*)(ob + pp0) = r;
        } else {
#pragma unroll
            for (int j = 0; j < 4; j++)
                if (pp0 + j < HW) ob[pp0 + j] = rp[j];
        }
    }
}

// ---------------------------------------------------------------------------
// Launch
// ---------------------------------------------------------------------------
extern "C" void kernel_launch(void* const* d_in, const int* in_sizes, int n_in,
                              void* d_out, int out_size)
{
    const float *f0 = nullptr, *f1 = nullptr, *f2 = nullptr, *w1 = nullptr;
    const float* bn1[4] = {nullptr, nullptr, nullptr, nullptr};
    const float* w2[3]  = {nullptr, nullptr, nullptr};
    const float* bn2[3][4];

    for (int i = 0; i < n_in; i++) {
        int sz = in_sizes[i];
        if (sz == 13107200)      f0 = (const float*)d_in[i];
        else if (sz == 6553600)  f1 = (const float*)d_in[i];
        else if (sz == 3276800)  f2 = (const float*)d_in[i];
        else if (sz == 972) {
            w1 = (const float*)d_in[i];
            for (int j = 0; j < 4; j++) bn1[j] = (const float*)d_in[i + 1 + j];
        } else if (sz == 16896) {
            w2[0] = (const float*)d_in[i];
            for (int j = 0; j < 4; j++) bn2[0][j] = (const float*)d_in[i + 1 + j];
        } else if (sz == 66560) {
            w2[1] = (const float*)d_in[i];
            for (int j = 0; j < 4; j++) bn2[1][j] = (const float*)d_in[i + 1 + j];
        } else if (sz == 264192) {
            w2[2] = (const float*)d_in[i];
            for (int j = 0; j < 4; j++) bn2[2][j] = (const float*)d_in[i + 1 + j];
        }
        // sizes 16 / 4 outside the bn groups = clip ids (unused by the math)
    }
    if (!f0 || !f1 || !f2 || !w1 || !w2[0] || !w2[1] || !w2[2]) return;

    cudaFuncSetAttribute(k_sim, cudaFuncAttributeMaxDynamicSharedMemorySize, 2 * 16 * HW2 * 16);
    cudaFuncSetAttribute(k_softconv1, cudaFuncAttributeMaxDynamicSharedMemorySize,
                         (243 * 128 + 12 * 128) * (int)sizeof(float));

    void *pr0, *pr1;
    cudaGetSymbolAddress(&pr0, g_pr0);
    cudaGetSymbolAddress(&pr1, g_pr1);
    void* simf;
    cudaGetSymbolAddress(&simf, g_simf);

    float* out0 = (float*)d_out;
    float* out1 = out0 + (size_t)B_ * 128 * 6400;
    float* out2 = out1 + (size_t)B_ * 256 * 1600;

    k_sim<<<dim3(NCHUNK, 12), 512, 2 * 16 * HW2 * 16>>>(f2);
    k_softconv1<<<dim3(4, B_), 512, (243 * 128 + 12 * 128) * sizeof(float)>>>(
        w1, bn1[0], bn1[1], bn1[2], bn1[3]);
    k_resize<<<(B_ * 4 * 6400 + 255) / 256, 256>>>((float*)pr0, 80, 80);
    k_resize<<<(B_ * 4 * 1600 + 255) / 256, 256>>>((float*)pr1, 40, 40);

    k_conv2<<<dim3(100, 2, B_), 256>>>(f0, (const float*)pr0, w2[0],
        bn2[0][0], bn2[0][1], bn2[0][2], bn2[0][3], out0, 128, 6400);
    k_conv2<<<dim3(25, 4, B_), 256>>>(f1, (const float*)pr1, w2[1],
        bn2[1][0], bn2[1][1], bn2[1][2], bn2[1][3], out1, 256, 1600);
    k_conv2<<<dim3(7, 8, B_), 256>>>(f2, (const float*)simf, w2[2],
        bn2[2][0], bn2[2][1], bn2[2][2], bn2[2][3], out2, 512, 400);
}

// round 3
// speedup vs baseline: 1.2273x; 1.2273x over previous
#include <cuda_runtime.h>
#include <cuda_bf16.h>

// Sim2: temporal cost-volume + softmax + 1x1convs on a 3-level pyramid.
//   k_sim      : cost volume partials, past-in-registers, padded cur window
//   k_softconv1: reduce 16 chunks + softmax(81) + conv1(243->4) + BN + SiLU
//   k_resize   : bilinear align_corners upsample
//   k_conv2    : per-level (C+4)->C 1x1 conv + BN + SiLU (templated SIMT GEMM)

#define B_    4
#define C2    512
#define HW2   400
#define NS_   81
#define NCH   16          // channel chunks of 32
#define CCH   32
#define WROWS 18          // 10 output rows + 2*4 halo
#define CROW  29          // padded row stride (28 cols used)

__device__ float g_Lpart[NCH * 12 * NS_ * HW2];   // 24.9 MB scratch
__device__ float g_simf[B_ * 4 * HW2];
__device__ float g_pr0[B_ * 4 * 6400];
__device__ float g_pr1[B_ * 4 * 1600];

// ---------------------------------------------------------------------------
// Kernel 1: cost volume partials. grid = (NCH, B, 2), 256 threads.
// smem: curS[32][18*29] zero-padded window (66.8KB) + pastS[3][32][200] (76.8KB)
// Thread owns one px; past values for 3 frames x 32 ch live in registers and
// are reused across all 81 displacements; cur comes from smem (1 LDS / diff3).
// ---------------------------------------------------------------------------
__global__ __launch_bounds__(256) void k_sim(const float* __restrict__ f2)
{
    int cc = blockIdx.x;            // 0..15
    int b  = blockIdx.y;
    int h  = blockIdx.z;            // px half: rows [h*10, h*10+10)

    extern __shared__ float sm[];
    float* curS  = sm;                        // [32][WROWS*CROW]
    float* pastS = sm + 32 * WROWS * CROW;    // [3][32][200]

    int tid = threadIdx.x;
    int r0  = h * 10;

    const float* curG = f2 + ((size_t)(b * 4 + 3) * C2 + cc * CCH) * HW2;

    // cur window (zero-padded halo)
    for (int i = tid; i < 32 * WROWS * 28; i += 256) {
        int c   = i / (WROWS * 28);
        int rem = i - c * (WROWS * 28);
        int wr  = rem / 28, wc = rem - wr * 28;
        int gy  = r0 + wr - 4, gx = wc - 4;
        float v = 0.f;
        if ((unsigned)gy < 20u && (unsigned)gx < 20u)
            v = curG[c * HW2 + gy * 20 + gx];
        curS[c * (WROWS * CROW) + wr * CROW + wc] = v;
    }
    // past frames (t = 0..2), rows [r0, r0+10)
    for (int i = tid; i < 3 * 32 * 200; i += 256) {
        int t   = i / (32 * 200);
        int rem = i - t * (32 * 200);
        int c   = rem / 200;
        int p   = rem - c * 200;
        pastS[i] = f2[((size_t)(b * 4 + t) * C2 + cc * CCH + c) * HW2 + r0 * 20 + p];
    }
    __syncthreads();

    if (tid < 200) {
        float pst[3][32];
#pragma unroll
        for (int t = 0; t < 3; t++)
#pragma unroll
            for (int c = 0; c < 32; c++)
                pst[t][c] = pastS[t * 6400 + c * 200 + tid];

        int lr  = tid / 20;
        int col = tid - lr * 20;
        size_t obase = (((size_t)cc * 12 + b * 3) * NS_) * HW2 + h * 200 + tid;

        for (int s = 0; s < NS_; s++) {
            int dy = s / 9, dx = s - dy * 9;
            const float* cp = curS + (lr + dy) * CROW + col + dx;
            float a0 = 0.f, a1 = 0.f, a2 = 0.f;
#pragma unroll
            for (int c = 0; c < 32; c++) {
                float cv = cp[c * (WROWS * CROW)];
                a0 -= fabsf(cv - pst[0][c]);
                a1 -= fabsf(cv - pst[1][c]);
                a2 -= fabsf(cv - pst[2][c]);
            }
            size_t o = obase + (size_t)s * HW2;
            g_Lpart[o]                       = a0;
            g_Lpart[o + (size_t)NS_ * HW2]   = a1;
            g_Lpart[o + (size_t)2 * NS_ * HW2] = a2;
        }
    }
}

// ---------------------------------------------------------------------------
// Kernel 2: reduce 16 chunks, softmax over 81 displacements (per t),
// conv1 (3*81 -> 4) + BN + SiLU. grid = (4, B), 512 threads.
// ---------------------------------------------------------------------------
__global__ __launch_bounds__(512) void k_softconv1(
    const float* __restrict__ w1,
    const float* __restrict__ g1, const float* __restrict__ b1,
    const float* __restrict__ m1, const float* __restrict__ v1)
{
    int b    = blockIdx.y;
    int lane = threadIdx.x & 127;
    int grp  = threadIdx.x >> 7;
    int px   = blockIdx.x * 128 + lane;
    bool act = px < HW2;

    extern __shared__ float Ls[];           // [243][128]
    float* opart = Ls + 243 * 128;          // [12][128]

    const float* base = g_Lpart + (size_t)(b * 3) * NS_ * HW2;

    for (int ts = grp; ts < 243; ts += 4) {
        float vsum = 0.f;
        if (act) {
            size_t off = (size_t)ts * HW2 + px;
#pragma unroll
            for (int cc = 0; cc < NCH; cc++)
                vsum += base[(size_t)cc * (12 * NS_ * HW2) + off];
        }
        Ls[ts * 128 + lane] = vsum;
    }
    __syncthreads();

    if (grp < 3) {
        int t = grp;
        float mx = -1e30f;
        for (int s = 0; s < 81; s++)
            mx = fmaxf(mx, Ls[(t * 81 + s) * 128 + lane]);
        float Z = 0.f;
        for (int s = 0; s < 81; s++)
            Z += __expf(Ls[(t * 81 + s) * 128 + lane] - mx);
        float rz = 1.f / Z;
        float o0 = 0, o1 = 0, o2 = 0, o3 = 0;
        for (int s = 0; s < 81; s++) {
            int k = t * 81 + s;
            float p = __expf(Ls[k * 128 + lane] - mx) * rz;
            o0 += w1[k] * p;       o1 += w1[243 + k] * p;
            o2 += w1[486 + k] * p; o3 += w1[729 + k] * p;
        }
        opart[(t * 4 + 0) * 128 + lane] = o0;
        opart[(t * 4 + 1) * 128 + lane] = o1;
        opart[(t * 4 + 2) * 128 + lane] = o2;
        opart[(t * 4 + 3) * 128 + lane] = o3;
    }
    __syncthreads();

    if (grp == 3 && act) {
#pragma unroll
        for (int oc = 0; oc < 4; oc++) {
            float o = opart[oc * 128 + lane] + opart[(4 + oc) * 128 + lane]
                    + opart[(8 + oc) * 128 + lane];
            float sc = g1[oc] * rsqrtf(v1[oc] + 1e-3f);
            float yv = (o - m1[oc]) * sc + b1[oc];
            g_simf[((size_t)b * 4 + oc) * HW2 + px] = yv / (1.f + __expf(-yv));
        }
    }
}

// ---------------------------------------------------------------------------
// Kernel 3: bilinear resize 20x20 -> Ho x Wo, align_corners=True
// ---------------------------------------------------------------------------
__global__ void k_resize(float* __restrict__ dst, int Ho, int Wo)
{
    int idx = blockIdx.x * 256 + threadIdx.x;
    int total = B_ * 4 * Ho * Wo;
    if (idx >= total) return;
    int xo = idx % Wo;
    int r  = idx / Wo;
    int yo = r % Ho;
    int bc = r / Ho;

    float cy = yo * (19.f / (float)(Ho - 1));
    float cx = xo * (19.f / (float)(Wo - 1));
    int y0 = (int)floorf(cy), x0 = (int)floorf(cx);
    int y1 = min(y0 + 1, 19), x1 = min(x0 + 1, 19);
    float wy = cy - (float)y0, wx = cx - (float)x0;

    const float* sp = g_simf + (size_t)bc * HW2;
    float v = (1.f - wy) * ((1.f - wx) * sp[y0 * 20 + x0] + wx * sp[y0 * 20 + x1])
            +         wy * ((1.f - wx) * sp[y1 * 20 + x0] + wx * sp[y1 * 20 + x1]);
    dst[idx] = v;
}

// ---------------------------------------------------------------------------
// Kernel 4: per-level 1x1 conv (C+4 -> C) + BN + SiLU.
// Templated SIMT GEMM: BM(o) x BN(px) tile, K-chunk 8, 256 threads (16x16),
// microtile (BM/16) x (BN/16) assembled from 4-wide register groups at
// offsets g*64 + t*4 (conflict-free float4 smem reads, a-operand broadcast).
// ---------------------------------------------------------------------------
template<int BM, int BN>
__global__ __launch_bounds__(256) void k_conv2(
    const float* __restrict__ feat,   // [B][4][C][HW], frame 3 used
    const float* __restrict__ pr,     // [B][4][HW]
    const float* __restrict__ w2,     // [C][C+4]
    const float* __restrict__ gg, const float* __restrict__ bb,
    const float* __restrict__ mm, const float* __restrict__ vv,
    float* __restrict__ out,          // [B][C][HW]
    int C, int HW)
{
    constexpr int TM = BM / 16;
    constexpr int TN = BN / 16;
    constexpr int GM = TM / 4;        // register groups of 4
    constexpr int GN = TN / 4;
    constexpr int BMP = BM + 4;       // pad to kill STS conflicts

    __shared__ float ws[8 * BMP];     // [k][o]
    __shared__ float xs[8 * BN];      // [k][px]

    int b     = blockIdx.z;
    int otile = blockIdx.y * BM;
    int ptile = blockIdx.x * BN;
    int K     = C + 4;

    const float* xbase = feat + (size_t)(b * 4 + 3) * C * HW;
    const float* prb   = pr + (size_t)b * 4 * HW;

    int tx = threadIdx.x & 15;
    int ty = threadIdx.x >> 4;

    float acc[TM][TN];
#pragma unroll
    for (int i = 0; i < TM; i++)
#pragma unroll
        for (int j = 0; j < TN; j++) acc[i][j] = 0.f;

    for (int k0 = 0; k0 < K; k0 += 8) {
        // weights: ws[k][o] (transposed)
#pragma unroll 2
        for (int i = threadIdx.x; i < 8 * BM; i += 256) {
            int k = i & 7, o = i >> 3;
            int kk = k0 + k;
            ws[k * BMP + o] = (kk < K) ? w2[(size_t)(otile + o) * K + kk] : 0.f;
        }
        // activations: xs[k][px], float4 (HW % 4 == 0, ptile 4-aligned)
        for (int i = threadIdx.x; i < 8 * (BN / 4); i += 256) {
            int k  = i / (BN / 4);
            int p4 = i - k * (BN / 4);
            int kk = k0 + k;
            int px0 = ptile + p4 * 4;
            float4 v = make_float4(0.f, 0.f, 0.f, 0.f);
            if (kk < K && px0 < HW)
                v = (kk < C) ? *(const float4*)(xbase + (size_t)kk * HW + px0)
                             : *(const float4*)(prb + (size_t)(kk - C) * HW + px0);
            *(float4*)&xs[k * BN + p4 * 4] = v;
        }
        __syncthreads();

#pragma unroll
        for (int k = 0; k < 8; k++) {
            float a[TM], xv[TN];
#pragma unroll
            for (int g = 0; g < GM; g++)
                *(float4*)&a[g * 4] = *(const float4*)&ws[k * BMP + g * 64 + ty * 4];
#pragma unroll
            for (int g = 0; g < GN; g++)
                *(float4*)&xv[g * 4] = *(const float4*)&xs[k * BN + g * 64 + tx * 4];
#pragma unroll
            for (int i = 0; i < TM; i++)
#pragma unroll
                for (int j = 0; j < TN; j++)
                    acc[i][j] += a[i] * xv[j];
        }
        __syncthreads();
    }

    // epilogue: BN + SiLU, float4 stores
#pragma unroll
    for (int gi = 0; gi < GM; gi++) {
#pragma unroll
        for (int ii = 0; ii < 4; ii++) {
            int oo = otile + gi * 64 + ty * 4 + ii;   // BM divides C -> in range
            float sc = gg[oo] * rsqrtf(vv[oo] + 1e-3f);
            float sh = bb[oo] - mm[oo] * sc;
            float* ob = out + (size_t)(b * C + oo) * HW;
#pragma unroll
            for (int gj = 0; gj < GN; gj++) {
                int pp0 = ptile + gj * 64 + tx * 4;
                if (pp0 < HW) {
                    float4 r;
                    float* rp = &r.x;
#pragma unroll
                    for (int jj = 0; jj < 4; jj++) {
                        float yv = acc[gi * 4 + ii][gj * 4 + jj] * sc + sh;
                        rp[jj] = yv / (1.f + __expf(-yv));
                    }
                    *(float4*)(ob + pp0) = r;
                }
            }
        }
    }
}

// ---------------------------------------------------------------------------
// Launch
// ---------------------------------------------------------------------------
extern "C" void kernel_launch(void* const* d_in, const int* in_sizes, int n_in,
                              void* d_out, int out_size)
{
    const float *f0 = nullptr, *f1 = nullptr, *f2 = nullptr, *w1 = nullptr;
    const float* bn1[4] = {nullptr, nullptr, nullptr, nullptr};
    const float* w2[3]  = {nullptr, nullptr, nullptr};
    const float* bn2[3][4];

    for (int i = 0; i < n_in; i++) {
        int sz = in_sizes[i];
        if (sz == 13107200)      f0 = (const float*)d_in[i];
        else if (sz == 6553600)  f1 = (const float*)d_in[i];
        else if (sz == 3276800)  f2 = (const float*)d_in[i];
        else if (sz == 972) {
            w1 = (const float*)d_in[i];
            for (int j = 0; j < 4; j++) bn1[j] = (const float*)d_in[i + 1 + j];
        } else if (sz == 16896) {
            w2[0] = (const float*)d_in[i];
            for (int j = 0; j < 4; j++) bn2[0][j] = (const float*)d_in[i + 1 + j];
        } else if (sz == 66560) {
            w2[1] = (const float*)d_in[i];
            for (int j = 0; j < 4; j++) bn2[1][j] = (const float*)d_in[i + 1 + j];
        } else if (sz == 264192) {
            w2[2] = (const float*)d_in[i];
            for (int j = 0; j < 4; j++) bn2[2][j] = (const float*)d_in[i + 1 + j];
        }
    }
    if (!f0 || !f1 || !f2 || !w1 || !w2[0] || !w2[1] || !w2[2]) return;

    int sim_smem = (32 * WROWS * CROW + 3 * 32 * 200) * (int)sizeof(float);
    cudaFuncSetAttribute(k_sim, cudaFuncAttributeMaxDynamicSharedMemorySize, sim_smem);
    cudaFuncSetAttribute(k_softconv1, cudaFuncAttributeMaxDynamicSharedMemorySize,
                         (243 * 128 + 12 * 128) * (int)sizeof(float));

    void *pr0, *pr1, *simf;
    cudaGetSymbolAddress(&pr0, g_pr0);
    cudaGetSymbolAddress(&pr1, g_pr1);
    cudaGetSymbolAddress(&simf, g_simf);

    float* out0 = (float*)d_out;
    float* out1 = out0 + (size_t)B_ * 128 * 6400;
    float* out2 = out1 + (size_t)B_ * 256 * 1600;

    k_sim<<<dim3(NCH, B_, 2), 256, sim_smem>>>(f2);
    k_softconv1<<<dim3(4, B_), 512, (243 * 128 + 12 * 128) * sizeof(float)>>>(
        w1, bn1[0], bn1[1], bn1[2], bn1[3]);
    k_resize<<<(B_ * 4 * 6400 + 255) / 256, 256>>>((float*)pr0, 80, 80);
    k_resize<<<(B_ * 4 * 1600 + 255) / 256, 256>>>((float*)pr1, 40, 40);

    k_conv2<128, 128><<<dim3(50, 1, B_), 256>>>(f0, (const float*)pr0, w2[0],
        bn2[0][0], bn2[0][1], bn2[0][2], bn2[0][3], out0, 128, 6400);
    k_conv2<128, 64><<<dim3(25, 2, B_), 256>>>(f1, (const float*)pr1, w2[1],
        bn2[1][0], bn2[1][1], bn2[1][2], bn2[1][3], out1, 256, 1600);
    k_conv2<64, 64><<<dim3(7, 8, B_), 256>>>(f2, (const float*)simf, w2[2],
        bn2[2][0], bn2[2][1], bn2[2][2], bn2[2][3], out2, 512, 400);
}

// round 4
// speedup vs baseline: 1.8787x; 1.5307x over previous
#include <cuda_runtime.h>
#include <cuda_bf16.h>
#include <cstdint>

// Sim2: temporal cost-volume + softmax + 1x1convs on a 3-level pyramid.
//   k_sim      : cost volume partials, past-in-registers, padded cur window
//   k_softconv1: reduce 16 chunks + softmax(81) + conv1(243->4) + BN + SiLU
//   k_resize   : bilinear align_corners upsample
//   k_conv2t   : unified 3-level (C+4)->C 1x1 conv + BN + SiLU,
//                split-bf16 tensor-core GEMM (mma.sync.m16n8k16)

#define B_    4
#define C2    512
#define HW2   400
#define NS_   81
#define NCH   16
#define CCH   32
#define WROWS 18
#define CROW  29

__device__ float g_Lpart[NCH * 12 * NS_ * HW2];
__device__ float g_simf[B_ * 4 * HW2];
__device__ float g_pr0[B_ * 4 * 6400];
__device__ float g_pr1[B_ * 4 * 1600];

// ---------------------------------------------------------------------------
// Kernel 1: cost volume partials. grid = (NCH, B, 2), 256 threads.
// ---------------------------------------------------------------------------
__global__ __launch_bounds__(256) void k_sim(const float* __restrict__ f2)
{
    int cc = blockIdx.x;
    int b  = blockIdx.y;
    int h  = blockIdx.z;

    extern __shared__ float sm[];
    float* curS  = sm;                        // [32][WROWS*CROW]
    float* pastS = sm + 32 * WROWS * CROW;    // [3][32][200]

    int tid = threadIdx.x;
    int r0  = h * 10;

    const float* curG = f2 + ((size_t)(b * 4 + 3) * C2 + cc * CCH) * HW2;

    for (int i = tid; i < 32 * WROWS * 28; i += 256) {
        int c   = i / (WROWS * 28);
        int rem = i - c * (WROWS * 28);
        int wr  = rem / 28, wc = rem - wr * 28;
        int gy  = r0 + wr - 4, gx = wc - 4;
        float v = 0.f;
        if ((unsigned)gy < 20u && (unsigned)gx < 20u)
            v = curG[c * HW2 + gy * 20 + gx];
        curS[c * (WROWS * CROW) + wr * CROW + wc] = v;
    }
    for (int i = tid; i < 3 * 32 * 200; i += 256) {
        int t   = i / (32 * 200);
        int rem = i - t * (32 * 200);
        int c   = rem / 200;
        int p   = rem - c * 200;
        pastS[i] = f2[((size_t)(b * 4 + t) * C2 + cc * CCH + c) * HW2 + r0 * 20 + p];
    }
    __syncthreads();

    if (tid < 200) {
        float pst[3][32];
#pragma unroll
        for (int t = 0; t < 3; t++)
#pragma unroll
            for (int c = 0; c < 32; c++)
                pst[t][c] = pastS[t * 6400 + c * 200 + tid];

        int lr  = tid / 20;
        int col = tid - lr * 20;
        size_t obase = (((size_t)cc * 12 + b * 3) * NS_) * HW2 + h * 200 + tid;

        for (int s = 0; s < NS_; s++) {
            int dy = s / 9, dx = s - dy * 9;
            const float* cp = curS + (lr + dy) * CROW + col + dx;
            float a0 = 0.f, a1 = 0.f, a2 = 0.f;
#pragma unroll
            for (int c = 0; c < 32; c++) {
                float cv = cp[c * (WROWS * CROW)];
                a0 -= fabsf(cv - pst[0][c]);
                a1 -= fabsf(cv - pst[1][c]);
                a2 -= fabsf(cv - pst[2][c]);
            }
            size_t o = obase + (size_t)s * HW2;
            g_Lpart[o]                         = a0;
            g_Lpart[o + (size_t)NS_ * HW2]     = a1;
            g_Lpart[o + (size_t)2 * NS_ * HW2] = a2;
        }
    }
}

// ---------------------------------------------------------------------------
// Kernel 2: reduce 16 chunks + softmax(81) + conv1 + BN + SiLU. grid=(4,B).
// ---------------------------------------------------------------------------
__global__ __launch_bounds__(512) void k_softconv1(
    const float* __restrict__ w1,
    const float* __restrict__ g1, const float* __restrict__ b1,
    const float* __restrict__ m1, const float* __restrict__ v1)
{
    int b    = blockIdx.y;
    int lane = threadIdx.x & 127;
    int grp  = threadIdx.x >> 7;
    int px   = blockIdx.x * 128 + lane;
    bool act = px < HW2;

    extern __shared__ float Ls[];
    float* opart = Ls + 243 * 128;

    const float* base = g_Lpart + (size_t)(b * 3) * NS_ * HW2;

    for (int ts = grp; ts < 243; ts += 4) {
        float vsum = 0.f;
        if (act) {
            size_t off = (size_t)ts * HW2 + px;
#pragma unroll
            for (int cc = 0; cc < NCH; cc++)
                vsum += base[(size_t)cc * (12 * NS_ * HW2) + off];
        }
        Ls[ts * 128 + lane] = vsum;
    }
    __syncthreads();

    if (grp < 3) {
        int t = grp;
        float mx = -1e30f;
        for (int s = 0; s < 81; s++)
            mx = fmaxf(mx, Ls[(t * 81 + s) * 128 + lane]);
        float Z = 0.f;
        for (int s = 0; s < 81; s++)
            Z += __expf(Ls[(t * 81 + s) * 128 + lane] - mx);
        float rz = 1.f / Z;
        float o0 = 0, o1 = 0, o2 = 0, o3 = 0;
        for (int s = 0; s < 81; s++) {
            int k = t * 81 + s;
            float p = __expf(Ls[k * 128 + lane] - mx) * rz;
            o0 += w1[k] * p;       o1 += w1[243 + k] * p;
            o2 += w1[486 + k] * p; o3 += w1[729 + k] * p;
        }
        opart[(t * 4 + 0) * 128 + lane] = o0;
        opart[(t * 4 + 1) * 128 + lane] = o1;
        opart[(t * 4 + 2) * 128 + lane] = o2;
        opart[(t * 4 + 3) * 128 + lane] = o3;
    }
    __syncthreads();

    if (grp == 3 && act) {
#pragma unroll
        for (int oc = 0; oc < 4; oc++) {
            float o = opart[oc * 128 + lane] + opart[(4 + oc) * 128 + lane]
                    + opart[(8 + oc) * 128 + lane];
            float sc = g1[oc] * rsqrtf(v1[oc] + 1e-3f);
            float yv = (o - m1[oc]) * sc + b1[oc];
            g_simf[((size_t)b * 4 + oc) * HW2 + px] = yv / (1.f + __expf(-yv));
        }
    }
}

// ---------------------------------------------------------------------------
// Kernel 3: bilinear resize 20x20 -> Ho x Wo, align_corners=True
// ---------------------------------------------------------------------------
__global__ void k_resize(float* __restrict__ dst, int Ho, int Wo)
{
    int idx = blockIdx.x * 256 + threadIdx.x;
    int total = B_ * 4 * Ho * Wo;
    if (idx >= total) return;
    int xo = idx % Wo;
    int r  = idx / Wo;
    int yo = r % Ho;
    int bc = r / Ho;

    float cy = yo * (19.f / (float)(Ho - 1));
    float cx = xo * (19.f / (float)(Wo - 1));
    int y0 = (int)floorf(cy), x0 = (int)floorf(cx);
    int y1 = min(y0 + 1, 19), x1 = min(x0 + 1, 19);
    float wy = cy - (float)y0, wx = cx - (float)x0;

    const float* sp = g_simf + (size_t)bc * HW2;
    float v = (1.f - wy) * ((1.f - wx) * sp[y0 * 20 + x0] + wx * sp[y0 * 20 + x1])
            +         wy * ((1.f - wx) * sp[y1 * 20 + x0] + wx * sp[y1 * 20 + x1]);
    dst[idx] = v;
}

// ---------------------------------------------------------------------------
// Kernel 4: unified tensor-core conv2 (split bf16, mma.sync.m16n8k16)
// Block tile: 64(o) x 128(px), K-chunks of 64. 256 threads = 8 warps (2x4).
// Warp tile 32x32. smem: Whi/Wlo [64][64] bf16, Xhi/Xlo [64][128] bf16 (48KB).
// ---------------------------------------------------------------------------
struct LvP {
    const float* feat; const float* pr; const float* w;
    const float* gg; const float* bb; const float* mm; const float* vv;
    float* out;
    int C, HW, nt, mt, blk0;
};
struct AllP { LvP lv[3]; };

__device__ __forceinline__ void ldsm4(uint32_t* r, uint32_t a) {
    asm volatile("ldmatrix.sync.aligned.m8n8.x4.shared.b16 {%0,%1,%2,%3},[%4];\n"
        : "=r"(r[0]), "=r"(r[1]), "=r"(r[2]), "=r"(r[3]) : "r"(a));
}
__device__ __forceinline__ void ldsm4t(uint32_t* r, uint32_t a) {
    asm volatile("ldmatrix.sync.aligned.m8n8.x4.trans.shared.b16 {%0,%1,%2,%3},[%4];\n"
        : "=r"(r[0]), "=r"(r[1]), "=r"(r[2]), "=r"(r[3]) : "r"(a));
}
__device__ __forceinline__ void mma16816(float* d, const uint32_t* a,
                                         uint32_t b0, uint32_t b1) {
    asm volatile("mma.sync.aligned.m16n8k16.row.col.f32.bf16.bf16.f32 "
        "{%0,%1,%2,%3},{%4,%5,%6,%7},{%8,%9},{%0,%1,%2,%3};\n"
        : "+f"(d[0]), "+f"(d[1]), "+f"(d[2]), "+f"(d[3])
        : "r"(a[0]), "r"(a[1]), "r"(a[2]), "r"(a[3]), "r"(b0), "r"(b1));
}
__device__ __forceinline__ void pack8(const float* v, uint4& hi, uint4& lo) {
    uint32_t h[4], l[4];
#pragma unroll
    for (int j = 0; j < 4; j++) {
        __nv_bfloat162 hh = __floats2bfloat162_rn(v[2*j], v[2*j+1]);
        float2 hf = __bfloat1622float2(hh);
        __nv_bfloat162 ll = __floats2bfloat162_rn(v[2*j] - hf.x, v[2*j+1] - hf.y);
        h[j] = *reinterpret_cast<uint32_t*>(&hh);
        l[j] = *reinterpret_cast<uint32_t*>(&ll);
    }
    hi = make_uint4(h[0], h[1], h[2], h[3]);
    lo = make_uint4(l[0], l[1], l[2], l[3]);
}

__global__ __launch_bounds__(256, 2) void k_conv2t(AllP P)
{
    extern __shared__ char smc[];
    const int OFF_WL = 8192, OFF_XH = 16384, OFF_XL = 32768;

    int bid = blockIdx.x;
    int li  = (bid >= P.lv[1].blk0) + (bid >= P.lv[2].blk0);
    LvP L = P.lv[li];

    int rb     = bid - L.blk0;
    int n_tile = rb % L.nt;
    int r2     = rb / L.nt;
    int m_tile = r2 % L.mt;
    int b      = r2 / L.mt;

    int ptile = n_tile * 128;
    int K     = L.C + 4;
    int nchunk = (K + 63) >> 6;

    int tid = threadIdx.x;
    int lane = tid & 31, wid = tid >> 5;
    int wm = wid >> 2, wn = wid & 3;

    uint32_t sb = (uint32_t)__cvta_generic_to_shared(smc);

    const float* xbase = L.feat + (size_t)(b * 4 + 3) * L.C * L.HW;
    const float* prb   = L.pr + (size_t)b * 4 * L.HW;

    float acc[2][4][4];
#pragma unroll
    for (int i = 0; i < 2; i++)
#pragma unroll
        for (int j = 0; j < 4; j++)
#pragma unroll
            for (int q = 0; q < 4; q++) acc[i][j][q] = 0.f;

    for (int c = 0; c < nchunk; c++) {
        int kbase = c * 64;
        // weights -> Whi/Wlo [o][k] swizzled
#pragma unroll
        for (int it = 0; it < 2; it++) {
            int item = tid + it * 256;
            int o = item >> 3, k0 = (item & 7) * 8;
            const float* src = L.w + (size_t)(m_tile * 64 + o) * K + kbase + k0;
            float v[8];
#pragma unroll
            for (int j = 0; j < 8; j++)
                v[j] = (kbase + k0 + j < K) ? src[j] : 0.f;
            uint4 hi, lo; pack8(v, hi, lo);
            int off = o * 128 + ((((k0 >> 3)) ^ (o & 7)) << 4);
            *(uint4*)(smc + off)          = hi;
            *(uint4*)(smc + OFF_WL + off) = lo;
        }
        // activations -> Xhi/Xlo [k][n] swizzled
#pragma unroll
        for (int it = 0; it < 4; it++) {
            int item = tid + it * 256;
            int kl = item >> 4;
            int n0 = (item & 15) * 8;
            int kk = kbase + kl;
            int px0 = ptile + n0;
            float v[8] = {0.f, 0.f, 0.f, 0.f, 0.f, 0.f, 0.f, 0.f};
            if (kk < K && px0 < L.HW) {
                const float* src = (kk < L.C)
                    ? xbase + (size_t)kk * L.HW + px0
                    : prb + (size_t)(kk - L.C) * L.HW + px0;
                *(float4*)v       = *(const float4*)src;
                *(float4*)(v + 4) = *(const float4*)(src + 4);
            }
            uint4 hi, lo; pack8(v, hi, lo);
            int off = kl * 256 + ((((n0 >> 3)) ^ (kl & 7)) << 4);
            *(uint4*)(smc + OFF_XH + off) = hi;
            *(uint4*)(smc + OFF_XL + off) = lo;
        }
        __syncthreads();

#pragma unroll
        for (int ks = 0; ks < 4; ks++) {
            uint32_t ah[2][4], al[2][4];
#pragma unroll
            for (int mi = 0; mi < 2; mi++) {
                int rr = wm * 32 + mi * 16 + (lane & 15);
                int ku = ks * 2 + (lane >> 4);
                uint32_t a = sb + rr * 128 + ((ku ^ (rr & 7)) << 4);
                ldsm4(ah[mi], a);
                ldsm4(al[mi], a + OFF_WL);
            }
            uint32_t bh[2][4], bl[2][4];
#pragma unroll
            for (int g = 0; g < 2; g++) {
                int kr = ks * 16 + (lane & 15);
                int n0 = wn * 32 + g * 16 + ((lane >> 4) * 8);
                uint32_t a = sb + OFF_XH + kr * 256 + (((n0 >> 3) ^ (kr & 7)) << 4);
                ldsm4t(bh[g], a);
                ldsm4t(bl[g], a + (OFF_XL - OFF_XH));
            }
#pragma unroll
            for (int mi = 0; mi < 2; mi++)
#pragma unroll
                for (int g = 0; g < 2; g++)
#pragma unroll
                    for (int t = 0; t < 2; t++) {
                        int ni = g * 2 + t;
                        mma16816(acc[mi][ni], ah[mi], bh[g][2*t], bh[g][2*t + 1]);
                        mma16816(acc[mi][ni], ah[mi], bl[g][2*t], bl[g][2*t + 1]);
                        mma16816(acc[mi][ni], al[mi], bh[g][2*t], bh[g][2*t + 1]);
                    }
        }
        __syncthreads();
    }

    // epilogue: BN + SiLU, float2 stores
    int ro = lane >> 2, co = (lane & 3) * 2;
#pragma unroll
    for (int mi = 0; mi < 2; mi++) {
#pragma unroll
        for (int half = 0; half < 2; half++) {
            int oo = m_tile * 64 + wm * 32 + mi * 16 + half * 8 + ro;
            float sc = L.gg[oo] * rsqrtf(L.vv[oo] + 1e-3f);
            float sh = L.bb[oo] - L.mm[oo] * sc;
            float* ob = L.out + (size_t)(b * L.C + oo) * L.HW;
#pragma unroll
            for (int ni = 0; ni < 4; ni++) {
                int px = ptile + wn * 32 + ni * 8 + co;
                if (px < L.HW) {
                    float y0 = acc[mi][ni][half * 2 + 0] * sc + sh;
                    float y1 = acc[mi][ni][half * 2 + 1] * sc + sh;
                    float2 r;
                    r.x = y0 / (1.f + __expf(-y0));
                    r.y = y1 / (1.f + __expf(-y1));
                    *(float2*)(ob + px) = r;
                }
            }
        }
    }
}

// ---------------------------------------------------------------------------
// Launch
// ---------------------------------------------------------------------------
extern "C" void kernel_launch(void* const* d_in, const int* in_sizes, int n_in,
                              void* d_out, int out_size)
{
    const float *f0 = nullptr, *f1 = nullptr, *f2 = nullptr, *w1 = nullptr;
    const float* bn1[4] = {nullptr, nullptr, nullptr, nullptr};
    const float* w2[3]  = {nullptr, nullptr, nullptr};
    const float* bn2[3][4];

    for (int i = 0; i < n_in; i++) {
        int sz = in_sizes[i];
        if (sz == 13107200)      f0 = (const float*)d_in[i];
        else if (sz == 6553600)  f1 = (const float*)d_in[i];
        else if (sz == 3276800)  f2 = (const float*)d_in[i];
        else if (sz == 972) {
            w1 = (const float*)d_in[i];
            for (int j = 0; j < 4; j++) bn1[j] = (const float*)d_in[i + 1 + j];
        } else if (sz == 16896) {
            w2[0] = (const float*)d_in[i];
            for (int j = 0; j < 4; j++) bn2[0][j] = (const float*)d_in[i + 1 + j];
        } else if (sz == 66560) {
            w2[1] = (const float*)d_in[i];
            for (int j = 0; j < 4; j++) bn2[1][j] = (const float*)d_in[i + 1 + j];
        } else if (sz == 264192) {
            w2[2] = (const float*)d_in[i];
            for (int j = 0; j < 4; j++) bn2[2][j] = (const float*)d_in[i + 1 + j];
        }
    }
    if (!f0 || !f1 || !f2 || !w1 || !w2[0] || !w2[1] || !w2[2]) return;

    int sim_smem = (32 * WROWS * CROW + 3 * 32 * 200) * (int)sizeof(float);
    cudaFuncSetAttribute(k_sim, cudaFuncAttributeMaxDynamicSharedMemorySize, sim_smem);
    cudaFuncSetAttribute(k_softconv1, cudaFuncAttributeMaxDynamicSharedMemorySize,
                         (243 * 128 + 12 * 128) * (int)sizeof(float));
    cudaFuncSetAttribute(k_conv2t, cudaFuncAttributeMaxDynamicSharedMemorySize, 49152);

    void *pr0, *pr1, *simf;
    cudaGetSymbolAddress(&pr0, g_pr0);
    cudaGetSymbolAddress(&pr1, g_pr1);
    cudaGetSymbolAddress(&simf, g_simf);

    float* out0 = (float*)d_out;
    float* out1 = out0 + (size_t)B_ * 128 * 6400;
    float* out2 = out1 + (size_t)B_ * 256 * 1600;

    k_sim<<<dim3(NCH, B_, 2), 256, sim_smem>>>(f2);
    k_softconv1<<<dim3(4, B_), 512, (243 * 128 + 12 * 128) * sizeof(float)>>>(
        w1, bn1[0], bn1[1], bn1[2], bn1[3]);
    k_resize<<<(B_ * 4 * 6400 + 255) / 256, 256>>>((float*)pr0, 80, 80);
    k_resize<<<(B_ * 4 * 1600 + 255) / 256, 256>>>((float*)pr1, 40, 40);

    AllP P;
    P.lv[0] = { f0, (const float*)pr0, w2[0],
                bn2[0][0], bn2[0][1], bn2[0][2], bn2[0][3],
                out0, 128, 6400, 50, 2, 0 };
    P.lv[1] = { f1, (const float*)pr1, w2[1],
                bn2[1][0], bn2[1][1], bn2[1][2], bn2[1][3],
                out1, 256, 1600, 13, 4, 400 };
    P.lv[2] = { f2, (const float*)simf, w2[2],
                bn2[2][0], bn2[2][1], bn2[2][2], bn2[2][3],
                out2, 512, 400, 4, 8, 608 };
    int total_blocks = 400 + 208 + 128;   // 736

    k_conv2t<<<total_blocks, 256, 49152>>>(P);
}

// round 5
// speedup vs baseline: 2.0355x; 1.0835x over previous
#include <cuda_runtime.h>
#include <cuda_bf16.h>
#include <cstdint>

// Sim2: temporal cost-volume + softmax + 1x1convs on a 3-level pyramid.
//   k_cvt_act  : fp32 -> split-bf16 (hi/lo) planes of frame-3 activations
//   k_cvt_w    : fp32 -> split-bf16 planes of the [C][C] weight blocks
//   k_sim      : cost volume partials, past-in-registers, padded cur window
//   k_softconv1: reduce 16 chunks + softmax(81) + conv1(243->4) + BN + SiLU
//   k_resize   : bilinear align_corners upsample
//   k_conv2t   : unified 3-level C->C tensor-core GEMM + pr-epilogue + BN + SiLU

#define B_    4
#define C2    512
#define HW2   400
#define NS_   81
#define NCH   16
#define CCH   32
#define WROWS 18
#define CROW  29

__device__ float g_Lpart[NCH * 12 * NS_ * HW2];
__device__ float g_simf[B_ * 4 * HW2];
__device__ float g_pr0[B_ * 4 * 6400];
__device__ float g_pr1[B_ * 4 * 1600];

// split-bf16 planes: act lvl0 @0 (3276800), lvl1 @3276800 (1638400), lvl2 @4915200 (819200)
__device__ __align__(16) __nv_bfloat16 g_xh[5734400];
__device__ __align__(16) __nv_bfloat16 g_xl[5734400];
// weights [o][k], k<C: lvl0 @0 (16384), lvl1 @16384 (65536), lvl2 @81920 (262144)
__device__ __align__(16) __nv_bfloat16 g_wh[344064];
__device__ __align__(16) __nv_bfloat16 g_wl[344064];

__device__ __forceinline__ void pack8(const float* v, uint4& hi, uint4& lo) {
    uint32_t h[4], l[4];
#pragma unroll
    for (int j = 0; j < 4; j++) {
        __nv_bfloat162 hh = __floats2bfloat162_rn(v[2*j], v[2*j+1]);
        float2 hf = __bfloat1622float2(hh);
        __nv_bfloat162 ll = __floats2bfloat162_rn(v[2*j] - hf.x, v[2*j+1] - hf.y);
        h[j] = *reinterpret_cast<uint32_t*>(&hh);
        l[j] = *reinterpret_cast<uint32_t*>(&ll);
    }
    hi = make_uint4(h[0], h[1], h[2], h[3]);
    lo = make_uint4(l[0], l[1], l[2], l[3]);
}

// ---------------------------------------------------------------------------
// Activation conversion: frame-3 of each level -> hi/lo bf16 planes.
// 716800 items x 8 floats. grid = 1400 x 512.
// ---------------------------------------------------------------------------
__global__ __launch_bounds__(512) void k_cvt_act(
    const float* __restrict__ f0, const float* __restrict__ f1,
    const float* __restrict__ f2)
{
    int idx = blockIdx.x * 512 + threadIdx.x;
    const float* src; size_t dstOff; int CHW, e;
    if (idx < 409600)      { src = f0; dstOff = 0;       CHW = 128 * 6400; e = idx * 8; }
    else if (idx < 614400) { src = f1; dstOff = 3276800; CHW = 256 * 1600; e = (idx - 409600) * 8; }
    else                   { src = f2; dstOff = 4915200; CHW = 512 * 400;  e = (idx - 614400) * 8; }
    int b = e / CHW;
    int r = e - b * CHW;
    const float* s = src + (size_t)(b * 4 + 3) * CHW + r;
    float v[8];
    *(float4*)v       = *(const float4*)s;
    *(float4*)(v + 4) = *(const float4*)(s + 4);
    uint4 hi, lo; pack8(v, hi, lo);
    *(uint4*)(g_xh + dstOff + (size_t)b * CHW + r) = hi;
    *(uint4*)(g_xl + dstOff + (size_t)b * CHW + r) = lo;
}

// ---------------------------------------------------------------------------
// Weight conversion: [C][C] block of each level's [C][C+4] weights.
// 43008 items x 8. grid = 168 x 256.
// ---------------------------------------------------------------------------
__global__ __launch_bounds__(256) void k_cvt_w(
    const float* __restrict__ w0, const float* __restrict__ w1,
    const float* __restrict__ w2)
{
    int idx = blockIdx.x * 256 + threadIdx.x;
    if (idx >= 43008) return;
    const float* w; size_t dstOff; int C, e;
    if (idx < 2048)       { w = w0; dstOff = 0;     C = 128; e = idx * 8; }
    else if (idx < 10240) { w = w1; dstOff = 16384; C = 256; e = (idx - 2048) * 8; }
    else                  { w = w2; dstOff = 81920; C = 512; e = (idx - 10240) * 8; }
    int o = e / C, k = e - o * C;
    const float* s = w + (size_t)o * (C + 4) + k;
    float v[8];
#pragma unroll
    for (int j = 0; j < 8; j++) v[j] = s[j];
    uint4 hi, lo; pack8(v, hi, lo);
    *(uint4*)(g_wh + dstOff + e) = hi;
    *(uint4*)(g_wl + dstOff + e) = lo;
}

// ---------------------------------------------------------------------------
// Kernel: cost volume partials. grid = (NCH, B, 2), 256 threads.
// ---------------------------------------------------------------------------
__global__ __launch_bounds__(256) void k_sim(const float* __restrict__ f2)
{
    int cc = blockIdx.x;
    int b  = blockIdx.y;
    int h  = blockIdx.z;

    extern __shared__ float sm[];
    float* curS  = sm;
    float* pastS = sm + 32 * WROWS * CROW;

    int tid = threadIdx.x;
    int r0  = h * 10;

    const float* curG = f2 + ((size_t)(b * 4 + 3) * C2 + cc * CCH) * HW2;

    for (int i = tid; i < 32 * WROWS * 28; i += 256) {
        int c   = i / (WROWS * 28);
        int rem = i - c * (WROWS * 28);
        int wr  = rem / 28, wc = rem - wr * 28;
        int gy  = r0 + wr - 4, gx = wc - 4;
        float v = 0.f;
        if ((unsigned)gy < 20u && (unsigned)gx < 20u)
            v = curG[c * HW2 + gy * 20 + gx];
        curS[c * (WROWS * CROW) + wr * CROW + wc] = v;
    }
    for (int i = tid; i < 3 * 32 * 200; i += 256) {
        int t   = i / (32 * 200);
        int rem = i - t * (32 * 200);
        int c   = rem / 200;
        int p   = rem - c * 200;
        pastS[i] = f2[((size_t)(b * 4 + t) * C2 + cc * CCH + c) * HW2 + r0 * 20 + p];
    }
    __syncthreads();

    if (tid < 200) {
        float pst[3][32];
#pragma unroll
        for (int t = 0; t < 3; t++)
#pragma unroll
            for (int c = 0; c < 32; c++)
                pst[t][c] = pastS[t * 6400 + c * 200 + tid];

        int lr  = tid / 20;
        int col = tid - lr * 20;
        size_t obase = (((size_t)cc * 12 + b * 3) * NS_) * HW2 + h * 200 + tid;

        for (int s = 0; s < NS_; s++) {
            int dy = s / 9, dx = s - dy * 9;
            const float* cp = curS + (lr + dy) * CROW + col + dx;
            float a0 = 0.f, a1 = 0.f, a2 = 0.f;
#pragma unroll
            for (int c = 0; c < 32; c++) {
                float cv = cp[c * (WROWS * CROW)];
                a0 -= fabsf(cv - pst[0][c]);
                a1 -= fabsf(cv - pst[1][c]);
                a2 -= fabsf(cv - pst[2][c]);
            }
            size_t o = obase + (size_t)s * HW2;
            g_Lpart[o]                         = a0;
            g_Lpart[o + (size_t)NS_ * HW2]     = a1;
            g_Lpart[o + (size_t)2 * NS_ * HW2] = a2;
        }
    }
}

// ---------------------------------------------------------------------------
// Kernel: reduce 16 chunks + softmax(81) + conv1 + BN + SiLU. grid=(4,B).
// ---------------------------------------------------------------------------
__global__ __launch_bounds__(512) void k_softconv1(
    const float* __restrict__ w1,
    const float* __restrict__ g1, const float* __restrict__ b1,
    const float* __restrict__ m1, const float* __restrict__ v1)
{
    int b    = blockIdx.y;
    int lane = threadIdx.x & 127;
    int grp  = threadIdx.x >> 7;
    int px   = blockIdx.x * 128 + lane;
    bool act = px < HW2;

    extern __shared__ float Ls[];
    float* opart = Ls + 243 * 128;

    const float* base = g_Lpart + (size_t)(b * 3) * NS_ * HW2;

    for (int ts = grp; ts < 243; ts += 4) {
        float vsum = 0.f;
        if (act) {
            size_t off = (size_t)ts * HW2 + px;
#pragma unroll
            for (int cc = 0; cc < NCH; cc++)
                vsum += base[(size_t)cc * (12 * NS_ * HW2) + off];
        }
        Ls[ts * 128 + lane] = vsum;
    }
    __syncthreads();

    if (grp < 3) {
        int t = grp;
        float mx = -1e30f;
        for (int s = 0; s < 81; s++)
            mx = fmaxf(mx, Ls[(t * 81 + s) * 128 + lane]);
        float Z = 0.f;
        for (int s = 0; s < 81; s++)
            Z += __expf(Ls[(t * 81 + s) * 128 + lane] - mx);
        float rz = 1.f / Z;
        float o0 = 0, o1 = 0, o2 = 0, o3 = 0;
        for (int s = 0; s < 81; s++) {
            int k = t * 81 + s;
            float p = __expf(Ls[k * 128 + lane] - mx) * rz;
            o0 += w1[k] * p;       o1 += w1[243 + k] * p;
            o2 += w1[486 + k] * p; o3 += w1[729 + k] * p;
        }
        opart[(t * 4 + 0) * 128 + lane] = o0;
        opart[(t * 4 + 1) * 128 + lane] = o1;
        opart[(t * 4 + 2) * 128 + lane] = o2;
        opart[(t * 4 + 3) * 128 + lane] = o3;
    }
    __syncthreads();

    if (grp == 3 && act) {
#pragma unroll
        for (int oc = 0; oc < 4; oc++) {
            float o = opart[oc * 128 + lane] + opart[(4 + oc) * 128 + lane]
                    + opart[(8 + oc) * 128 + lane];
            float sc = g1[oc] * rsqrtf(v1[oc] + 1e-3f);
            float yv = (o - m1[oc]) * sc + b1[oc];
            g_simf[((size_t)b * 4 + oc) * HW2 + px] = yv / (1.f + __expf(-yv));
        }
    }
}

// ---------------------------------------------------------------------------
// Kernel: bilinear resize 20x20 -> Ho x Wo, align_corners=True
// ---------------------------------------------------------------------------
__global__ void k_resize(float* __restrict__ dst, int Ho, int Wo)
{
    int idx = blockIdx.x * 256 + threadIdx.x;
    int total = B_ * 4 * Ho * Wo;
    if (idx >= total) return;
    int xo = idx % Wo;
    int r  = idx / Wo;
    int yo = r % Ho;
    int bc = r / Ho;

    float cy = yo * (19.f / (float)(Ho - 1));
    float cx = xo * (19.f / (float)(Wo - 1));
    int y0 = (int)floorf(cy), x0 = (int)floorf(cx);
    int y1 = min(y0 + 1, 19), x1 = min(x0 + 1, 19);
    float wy = cy - (float)y0, wx = cx - (float)x0;

    const float* sp = g_simf + (size_t)bc * HW2;
    float v = (1.f - wy) * ((1.f - wx) * sp[y0 * 20 + x0] + wx * sp[y0 * 20 + x1])
            +         wy * ((1.f - wx) * sp[y1 * 20 + x0] + wx * sp[y1 * 20 + x1]);
    dst[idx] = v;
}

// ---------------------------------------------------------------------------
// Kernel: unified tensor-core conv2 (pre-split bf16, mma.sync.m16n8k16)
// Block tile 64(o) x 128(px), K-chunks of 64 (nchunk = C/64 exactly; the 4
// pr channels are added in fp32 in the epilogue). 8 warps (2x4), warp 32x32.
// smem: WH/WL [64][64], XH/XL [64][128] bf16 swizzled + prS[4][128] + wprS[64][4]
// ---------------------------------------------------------------------------
struct LvP {
    const float* pr; const float* w;
    const float* gg; const float* bb; const float* mm; const float* vv;
    const __nv_bfloat16 *xh, *xl, *wh, *wl;
    float* out;
    int C, HW, nt, mt, blk0;
};
struct AllP { LvP lv[3]; };

__device__ __forceinline__ void ldsm4(uint32_t* r, uint32_t a) {
    asm volatile("ldmatrix.sync.aligned.m8n8.x4.shared.b16 {%0,%1,%2,%3},[%4];\n"
        : "=r"(r[0]), "=r"(r[1]), "=r"(r[2]), "=r"(r[3]) : "r"(a));
}
__device__ __forceinline__ void ldsm4t(uint32_t* r, uint32_t a) {
    asm volatile("ldmatrix.sync.aligned.m8n8.x4.trans.shared.b16 {%0,%1,%2,%3},[%4];\n"
        : "=r"(r[0]), "=r"(r[1]), "=r"(r[2]), "=r"(r[3]) : "r"(a));
}
__device__ __forceinline__ void mma16816(float* d, const uint32_t* a,
                                         uint32_t b0, uint32_t b1) {
    asm volatile("mma.sync.aligned.m16n8k16.row.col.f32.bf16.bf16.f32 "
        "{%0,%1,%2,%3},{%4,%5,%6,%7},{%8,%9},{%0,%1,%2,%3};\n"
        : "+f"(d[0]), "+f"(d[1]), "+f"(d[2]), "+f"(d[3])
        : "r"(a[0]), "r"(a[1]), "r"(a[2]), "r"(a[3]), "r"(b0), "r"(b1));
}

__global__ __launch_bounds__(256, 2) void k_conv2t(AllP P)
{
    extern __shared__ char smc[];
    const int OFF_WL = 8192, OFF_XH = 16384, OFF_XL = 32768;
    float* prS  = (float*)(smc + 49152);   // [4][128]
    float* wprS = (float*)(smc + 51200);   // [64][4]

    int bid = blockIdx.x;
    int li  = (bid >= P.lv[1].blk0) + (bid >= P.lv[2].blk0);
    LvP L = P.lv[li];

    int rb     = bid - L.blk0;
    int n_tile = rb % L.nt;
    int r2     = rb / L.nt;
    int m_tile = r2 % L.mt;
    int b      = r2 / L.mt;

    int ptile  = n_tile * 128;
    int K      = L.C + 4;
    int nchunk = L.C >> 6;

    int tid = threadIdx.x;
    int lane = tid & 31, wid = tid >> 5;
    int wm = wid >> 2, wn = wid & 3;

    uint32_t sb = (uint32_t)__cvta_generic_to_shared(smc);

    const __nv_bfloat16* xhb = L.xh + (size_t)b * L.C * L.HW;
    const __nv_bfloat16* xlb = L.xl + (size_t)b * L.C * L.HW;
    const __nv_bfloat16* whb = L.wh + (size_t)m_tile * 64 * L.C;
    const __nv_bfloat16* wlb = L.wl + (size_t)m_tile * 64 * L.C;
    const float* prb = L.pr + (size_t)b * 4 * L.HW;

    // pr tile + pr weights (read once; ordered by first in-loop barrier)
    for (int i = tid; i < 512; i += 256) {
        int j = i >> 7, n = i & 127;
        int px = ptile + n;
        prS[i] = (px < L.HW) ? prb[(size_t)j * L.HW + px] : 0.f;
    }
    {
        int o = tid >> 2, j = tid & 3;
        wprS[tid] = L.w[(size_t)(m_tile * 64 + o) * K + L.C + j];
    }

    float acc[2][4][4];
#pragma unroll
    for (int i = 0; i < 2; i++)
#pragma unroll
        for (int j = 0; j < 4; j++)
#pragma unroll
            for (int q = 0; q < 4; q++) acc[i][j][q] = 0.f;

    for (int c = 0; c < nchunk; c++) {
        int kbase = c * 64;
        // weights: 512 16B-units per plane
#pragma unroll
        for (int it = 0; it < 2; it++) {
            int item = tid + it * 256;
            int o = item >> 3, u = item & 7;
            size_t si = (size_t)o * L.C + kbase + u * 8;
            int off = o * 128 + (((u) ^ (o & 7)) << 4);
            *(uint4*)(smc + off)          = *(const uint4*)(whb + si);
            *(uint4*)(smc + OFF_WL + off) = *(const uint4*)(wlb + si);
        }
        // activations: 1024 16B-units per plane
#pragma unroll
        for (int it = 0; it < 4; it++) {
            int item = tid + it * 256;
            int kl = item >> 4, u = item & 15;
            int px0 = ptile + u * 8;
            uint4 vh = make_uint4(0, 0, 0, 0), vl = vh;
            if (px0 < L.HW) {
                size_t si = (size_t)(kbase + kl) * L.HW + px0;
                vh = *(const uint4*)(xhb + si);
                vl = *(const uint4*)(xlb + si);
            }
            int off = kl * 256 + (((u) ^ (kl & 7)) << 4);
            *(uint4*)(smc + OFF_XH + off) = vh;
            *(uint4*)(smc + OFF_XL + off) = vl;
        }
        __syncthreads();

#pragma unroll
        for (int ks = 0; ks < 4; ks++) {
            uint32_t ah[2][4], al[2][4];
#pragma unroll
            for (int mi = 0; mi < 2; mi++) {
                int rr = wm * 32 + mi * 16 + (lane & 15);
                int ku = ks * 2 + (lane >> 4);
                uint32_t a = sb + rr * 128 + ((ku ^ (rr & 7)) << 4);
                ldsm4(ah[mi], a);
                ldsm4(al[mi], a + OFF_WL);
            }
            uint32_t bh[2][4], bl[2][4];
#pragma unroll
            for (int g = 0; g < 2; g++) {
                int kr = ks * 16 + (lane & 15);
                int n0 = wn * 32 + g * 16 + ((lane >> 4) * 8);
                uint32_t a = sb + OFF_XH + kr * 256 + (((n0 >> 3) ^ (kr & 7)) << 4);
                ldsm4t(bh[g], a);
                ldsm4t(bl[g], a + (OFF_XL - OFF_XH));
            }
#pragma unroll
            for (int mi = 0; mi < 2; mi++)
#pragma unroll
                for (int g = 0; g < 2; g++)
#pragma unroll
                    for (int t = 0; t < 2; t++) {
                        int ni = g * 2 + t;
                        mma16816(acc[mi][ni], ah[mi], bh[g][2*t], bh[g][2*t + 1]);
                        mma16816(acc[mi][ni], ah[mi], bl[g][2*t], bl[g][2*t + 1]);
                        mma16816(acc[mi][ni], al[mi], bh[g][2*t], bh[g][2*t + 1]);
                    }
        }
        __syncthreads();
    }

    // epilogue: + pr contribution (fp32), BN + SiLU, float2 stores
    int ro = lane >> 2, co = (lane & 3) * 2;
#pragma unroll
    for (int mi = 0; mi < 2; mi++) {
#pragma unroll
        for (int half = 0; half < 2; half++) {
            int rloc = wm * 32 + mi * 16 + half * 8 + ro;
            int oo = m_tile * 64 + rloc;
            float w0 = wprS[rloc * 4 + 0], w1 = wprS[rloc * 4 + 1];
            float w2 = wprS[rloc * 4 + 2], w3 = wprS[rloc * 4 + 3];
            float sc = L.gg[oo] * rsqrtf(L.vv[oo] + 1e-3f);
            float sh = L.bb[oo] - L.mm[oo] * sc;
            float* ob = L.out + (size_t)(b * L.C + oo) * L.HW;
#pragma unroll
            for (int ni = 0; ni < 4; ni++) {
                int nloc = wn * 32 + ni * 8 + co;
                int px = ptile + nloc;
                if (px < L.HW) {
                    float p0 = acc[mi][ni][half * 2 + 0]
                             + w0 * prS[nloc]       + w1 * prS[128 + nloc]
                             + w2 * prS[256 + nloc] + w3 * prS[384 + nloc];
                    float p1 = acc[mi][ni][half * 2 + 1]
                             + w0 * prS[nloc + 1]       + w1 * prS[128 + nloc + 1]
                             + w2 * prS[256 + nloc + 1] + w3 * prS[384 + nloc + 1];
                    float y0 = p0 * sc + sh;
                    float y1 = p1 * sc + sh;
                    float2 r;
                    r.x = y0 / (1.f + __expf(-y0));
                    r.y = y1 / (1.f + __expf(-y1));
                    *(float2*)(ob + px) = r;
                }
            }
        }
    }
}

// ---------------------------------------------------------------------------
// Launch
// ---------------------------------------------------------------------------
extern "C" void kernel_launch(void* const* d_in, const int* in_sizes, int n_in,
                              void* d_out, int out_size)
{
    const float *f0 = nullptr, *f1 = nullptr, *f2 = nullptr, *w1 = nullptr;
    const float* bn1[4] = {nullptr, nullptr, nullptr, nullptr};
    const float* w2[3]  = {nullptr, nullptr, nullptr};
    const float* bn2[3][4];

    for (int i = 0; i < n_in; i++) {
        int sz = in_sizes[i];
        if (sz == 13107200)      f0 = (const float*)d_in[i];
        else if (sz == 6553600)  f1 = (const float*)d_in[i];
        else if (sz == 3276800)  f2 = (const float*)d_in[i];
        else if (sz == 972) {
            w1 = (const float*)d_in[i];
            for (int j = 0; j < 4; j++) bn1[j] = (const float*)d_in[i + 1 + j];
        } else if (sz == 16896) {
            w2[0] = (const float*)d_in[i];
            for (int j = 0; j < 4; j++) bn2[0][j] = (const float*)d_in[i + 1 + j];
        } else if (sz == 66560) {
            w2[1] = (const float*)d_in[i];
            for (int j = 0; j < 4; j++) bn2[1][j] = (const float*)d_in[i + 1 + j];
        } else if (sz == 264192) {
            w2[2] = (const float*)d_in[i];
            for (int j = 0; j < 4; j++) bn2[2][j] = (const float*)d_in[i + 1 + j];
        }
    }
    if (!f0 || !f1 || !f2 || !w1 || !w2[0] || !w2[1] || !w2[2]) return;

    int sim_smem = (32 * WROWS * CROW + 3 * 32 * 200) * (int)sizeof(float);
    cudaFuncSetAttribute(k_sim, cudaFuncAttributeMaxDynamicSharedMemorySize, sim_smem);
    cudaFuncSetAttribute(k_softconv1, cudaFuncAttributeMaxDynamicSharedMemorySize,
                         (243 * 128 + 12 * 128) * (int)sizeof(float));
    cudaFuncSetAttribute(k_conv2t, cudaFuncAttributeMaxDynamicSharedMemorySize, 52224);

    void *pr0, *pr1, *simf, *xh, *xl, *wh, *wl;
    cudaGetSymbolAddress(&pr0, g_pr0);
    cudaGetSymbolAddress(&pr1, g_pr1);
    cudaGetSymbolAddress(&simf, g_simf);
    cudaGetSymbolAddress(&xh, g_xh);
    cudaGetSymbolAddress(&xl, g_xl);
    cudaGetSymbolAddress(&wh, g_wh);
    cudaGetSymbolAddress(&wl, g_wl);
    const __nv_bfloat16* XH = (const __nv_bfloat16*)xh;
    const __nv_bfloat16* XL = (const __nv_bfloat16*)xl;
    const __nv_bfloat16* WH = (const __nv_bfloat16*)wh;
    const __nv_bfloat16* WL = (const __nv_bfloat16*)wl;

    float* out0 = (float*)d_out;
    float* out1 = out0 + (size_t)B_ * 128 * 6400;
    float* out2 = out1 + (size_t)B_ * 256 * 1600;

    k_cvt_act<<<1400, 512>>>(f0, f1, f2);
    k_cvt_w<<<168, 256>>>(w2[0], w2[1], w2[2]);
    k_sim<<<dim3(NCH, B_, 2), 256, sim_smem>>>(f2);
    k_softconv1<<<dim3(4, B_), 512, (243 * 128 + 12 * 128) * sizeof(float)>>>(
        w1, bn1[0], bn1[1], bn1[2], bn1[3]);
    k_resize<<<(B_ * 4 * 6400 + 255) / 256, 256>>>((float*)pr0, 80, 80);
    k_resize<<<(B_ * 4 * 1600 + 255) / 256, 256>>>((float*)pr1, 40, 40);

    AllP P;
    P.lv[0] = { (const float*)pr0, w2[0],
                bn2[0][0], bn2[0][1], bn2[0][2], bn2[0][3],
                XH, XL, WH, WL,
                out0, 128, 6400, 50, 2, 0 };
    P.lv[1] = { (const float*)pr1, w2[1],
                bn2[1][0], bn2[1][1], bn2[1][2], bn2[1][3],
                XH + 3276800, XL + 3276800, WH + 16384, WL + 16384,
                out1, 256, 1600, 13, 4, 400 };
    P.lv[2] = { (const float*)simf, w2[2],
                bn2[2][0], bn2[2][1], bn2[2][2], bn2[2][3],
                XH + 4915200, XL + 4915200, WH + 81920, WL + 81920,
                out2, 512, 400, 4, 8, 608 };
    int total_blocks = 400 + 208 + 128;   // 736

    k_conv2t<<<total_blocks, 256, 52224>>>(P);
}

// round 6
// speedup vs baseline: 2.6535x; 1.3036x over previous
#include <cuda_runtime.h>
#include <cuda_bf16.h>
#include <cstdint>

// Sim2: temporal cost-volume + softmax + 1x1convs on a 3-level pyramid.
//   k_cvt_act  : fp32 -> split-bf16 (hi/lo) planes of frame-3 activations
//   k_cvt_w    : fp32 -> split-bf16 planes of the [C][C] weight blocks
//   k_sim      : cost volume partials, past-in-registers, padded cur window
//   k_reduce   : wide 16-chunk fold -> g_L (full-chip streaming)
//   k_softmax1 : in-register softmax(81) + conv1(243->4) + BN + SiLU
//   k_resize   : bilinear align_corners upsample
//   k_conv2t   : unified 3-level C->C tensor-core GEMM + pr-epilogue + BN + SiLU

#define B_    4
#define C2    512
#define HW2   400
#define NS_   81
#define NCH   16
#define CCH   32
#define WROWS 18
#define CROW  29

__device__ float g_Lpart[NCH * 12 * NS_ * HW2];
__device__ float g_L[12 * NS_ * HW2];
__device__ float g_simf[B_ * 4 * HW2];
__device__ float g_pr0[B_ * 4 * 6400];
__device__ float g_pr1[B_ * 4 * 1600];

// split-bf16 planes: act lvl0 @0, lvl1 @3276800, lvl2 @4915200
__device__ __align__(16) __nv_bfloat16 g_xh[5734400];
__device__ __align__(16) __nv_bfloat16 g_xl[5734400];
// weights [o][k], k<C: lvl0 @0, lvl1 @16384, lvl2 @81920
__device__ __align__(16) __nv_bfloat16 g_wh[344064];
__device__ __align__(16) __nv_bfloat16 g_wl[344064];

__device__ __forceinline__ void pack8(const float* v, uint4& hi, uint4& lo) {
    uint32_t h[4], l[4];
#pragma unroll
    for (int j = 0; j < 4; j++) {
        __nv_bfloat162 hh = __floats2bfloat162_rn(v[2*j], v[2*j+1]);
        float2 hf = __bfloat1622float2(hh);
        __nv_bfloat162 ll = __floats2bfloat162_rn(v[2*j] - hf.x, v[2*j+1] - hf.y);
        h[j] = *reinterpret_cast<uint32_t*>(&hh);
        l[j] = *reinterpret_cast<uint32_t*>(&ll);
    }
    hi = make_uint4(h[0], h[1], h[2], h[3]);
    lo = make_uint4(l[0], l[1], l[2], l[3]);
}

// ---------------------------------------------------------------------------
// Activation conversion. 716800 items x 8 floats. grid = 1400 x 512.
// ---------------------------------------------------------------------------
__global__ __launch_bounds__(512) void k_cvt_act(
    const float* __restrict__ f0, const float* __restrict__ f1,
    const float* __restrict__ f2)
{
    int idx = blockIdx.x * 512 + threadIdx.x;
    const float* src; size_t dstOff; int CHW, e;
    if (idx < 409600)      { src = f0; dstOff = 0;       CHW = 128 * 6400; e = idx * 8; }
    else if (idx < 614400) { src = f1; dstOff = 3276800; CHW = 256 * 1600; e = (idx - 409600) * 8; }
    else                   { src = f2; dstOff = 4915200; CHW = 512 * 400;  e = (idx - 614400) * 8; }
    int b = e / CHW;
    int r = e - b * CHW;
    const float* s = src + (size_t)(b * 4 + 3) * CHW + r;
    float v[8];
    *(float4*)v       = *(const float4*)s;
    *(float4*)(v + 4) = *(const float4*)(s + 4);
    uint4 hi, lo; pack8(v, hi, lo);
    *(uint4*)(g_xh + dstOff + (size_t)b * CHW + r) = hi;
    *(uint4*)(g_xl + dstOff + (size_t)b * CHW + r) = lo;
}

// ---------------------------------------------------------------------------
// Weight conversion: [C][C] blocks. 43008 items x 8. grid = 168 x 256.
// ---------------------------------------------------------------------------
__global__ __launch_bounds__(256) void k_cvt_w(
    const float* __restrict__ w0, const float* __restrict__ w1,
    const float* __restrict__ w2)
{
    int idx = blockIdx.x * 256 + threadIdx.x;
    if (idx >= 43008) return;
    const float* w; size_t dstOff; int C, e;
    if (idx < 2048)       { w = w0; dstOff = 0;     C = 128; e = idx * 8; }
    else if (idx < 10240) { w = w1; dstOff = 16384; C = 256; e = (idx - 2048) * 8; }
    else                  { w = w2; dstOff = 81920; C = 512; e = (idx - 10240) * 8; }
    int o = e / C, k = e - o * C;
    const float* s = w + (size_t)o * (C + 4) + k;
    float v[8];
#pragma unroll
    for (int j = 0; j < 8; j++) v[j] = s[j];
    uint4 hi, lo; pack8(v, hi, lo);
    *(uint4*)(g_wh + dstOff + e) = hi;
    *(uint4*)(g_wl + dstOff + e) = lo;
}

// ---------------------------------------------------------------------------
// Kernel: cost volume partials. grid = (NCH, B, 2), 256 threads.
// ---------------------------------------------------------------------------
__global__ __launch_bounds__(256) void k_sim(const float* __restrict__ f2)
{
    int cc = blockIdx.x;
    int b  = blockIdx.y;
    int h  = blockIdx.z;

    extern __shared__ float sm[];
    float* curS  = sm;
    float* pastS = sm + 32 * WROWS * CROW;

    int tid = threadIdx.x;
    int r0  = h * 10;

    const float* curG = f2 + ((size_t)(b * 4 + 3) * C2 + cc * CCH) * HW2;

    for (int i = tid; i < 32 * WROWS * 28; i += 256) {
        int c   = i / (WROWS * 28);
        int rem = i - c * (WROWS * 28);
        int wr  = rem / 28, wc = rem - wr * 28;
        int gy  = r0 + wr - 4, gx = wc - 4;
        float v = 0.f;
        if ((unsigned)gy < 20u && (unsigned)gx < 20u)
            v = curG[c * HW2 + gy * 20 + gx];
        curS[c * (WROWS * CROW) + wr * CROW + wc] = v;
    }
    for (int i = tid; i < 3 * 32 * 200; i += 256) {
        int t   = i / (32 * 200);
        int rem = i - t * (32 * 200);
        int c   = rem / 200;
        int p   = rem - c * 200;
        pastS[i] = f2[((size_t)(b * 4 + t) * C2 + cc * CCH + c) * HW2 + r0 * 20 + p];
    }
    __syncthreads();

    if (tid < 200) {
        float pst[3][32];
#pragma unroll
        for (int t = 0; t < 3; t++)
#pragma unroll
            for (int c = 0; c < 32; c++)
                pst[t][c] = pastS[t * 6400 + c * 200 + tid];

        int lr  = tid / 20;
        int col = tid - lr * 20;
        size_t obase = (((size_t)cc * 12 + b * 3) * NS_) * HW2 + h * 200 + tid;

        for (int s = 0; s < NS_; s++) {
            int dy = s / 9, dx = s - dy * 9;
            const float* cp = curS + (lr + dy) * CROW + col + dx;
            float a0 = 0.f, a1 = 0.f, a2 = 0.f;
#pragma unroll
            for (int c = 0; c < 32; c++) {
                float cv = cp[c * (WROWS * CROW)];
                a0 -= fabsf(cv - pst[0][c]);
                a1 -= fabsf(cv - pst[1][c]);
                a2 -= fabsf(cv - pst[2][c]);
            }
            size_t o = obase + (size_t)s * HW2;
            g_Lpart[o]                         = a0;
            g_Lpart[o + (size_t)NS_ * HW2]     = a1;
            g_Lpart[o + (size_t)2 * NS_ * HW2] = a2;
        }
    }
}

// ---------------------------------------------------------------------------
// Kernel: wide 16-chunk fold. 97200 float4 outputs. grid = 380 x 256.
// ---------------------------------------------------------------------------
__global__ __launch_bounds__(256) void k_reduce()
{
    int e = blockIdx.x * 256 + threadIdx.x;
    if (e >= 97200) return;
    const float4* src = (const float4*)g_Lpart + e;
    float4 a = src[0];
#pragma unroll
    for (int cc = 1; cc < NCH; cc++) {
        float4 v = src[(size_t)cc * 97200];
        a.x += v.x; a.y += v.y; a.z += v.z; a.w += v.w;
    }
    ((float4*)g_L)[e] = a;
}

// ---------------------------------------------------------------------------
// Kernel: in-register softmax(81) + conv1(243->4) + BN + SiLU.
// grid = (4, B), 384 threads = 3 t-groups x 128 px-lanes (100 active).
// ---------------------------------------------------------------------------
__global__ __launch_bounds__(384) void k_softmax1(
    const float* __restrict__ w1,
    const float* __restrict__ g1, const float* __restrict__ b1,
    const float* __restrict__ m1, const float* __restrict__ v1)
{
    __shared__ float w1s[972];
    __shared__ float opart[12 * 128];

    int b    = blockIdx.y;
    int tid  = threadIdx.x;
    int t    = tid >> 7;
    int lane = tid & 127;
    int px   = blockIdx.x * 100 + lane;

    for (int i = tid; i < 972; i += 384) w1s[i] = w1[i];
    __syncthreads();

    if (lane < 100) {
        const float* Lb = g_L + ((size_t)(b * 3 + t) * NS_) * HW2 + px;
        float e[NS_];
#pragma unroll
        for (int s = 0; s < NS_; s++) e[s] = Lb[(size_t)s * HW2];
        float mx = -1e30f;
#pragma unroll
        for (int s = 0; s < NS_; s++) mx = fmaxf(mx, e[s]);
        float Z = 0.f;
#pragma unroll
        for (int s = 0; s < NS_; s++) { e[s] = __expf(e[s] - mx); Z += e[s]; }
        float rz = 1.f / Z;
        float o0 = 0, o1 = 0, o2 = 0, o3 = 0;
        const float* wt = w1s + t * 81;
#pragma unroll
        for (int s = 0; s < NS_; s++) {
            float p = e[s] * rz;
            o0 += wt[s] * p;       o1 += wt[243 + s] * p;
            o2 += wt[486 + s] * p; o3 += wt[729 + s] * p;
        }
        opart[(t * 4 + 0) * 128 + lane] = o0;
        opart[(t * 4 + 1) * 128 + lane] = o1;
        opart[(t * 4 + 2) * 128 + lane] = o2;
        opart[(t * 4 + 3) * 128 + lane] = o3;
    }
    __syncthreads();

    if (t == 0 && lane < 100) {
#pragma unroll
        for (int oc = 0; oc < 4; oc++) {
            float o = opart[oc * 128 + lane] + opart[(4 + oc) * 128 + lane]
                    + opart[(8 + oc) * 128 + lane];
            float sc = g1[oc] * rsqrtf(v1[oc] + 1e-3f);
            float yv = (o - m1[oc]) * sc + b1[oc];
            g_simf[((size_t)b * 4 + oc) * HW2 + px] = yv / (1.f + __expf(-yv));
        }
    }
}

// ---------------------------------------------------------------------------
// Kernel: bilinear resize 20x20 -> Ho x Wo, align_corners=True
// ---------------------------------------------------------------------------
__global__ void k_resize(float* __restrict__ dst, int Ho, int Wo)
{
    int idx = blockIdx.x * 256 + threadIdx.x;
    int total = B_ * 4 * Ho * Wo;
    if (idx >= total) return;
    int xo = idx % Wo;
    int r  = idx / Wo;
    int yo = r % Ho;
    int bc = r / Ho;

    float cy = yo * (19.f / (float)(Ho - 1));
    float cx = xo * (19.f / (float)(Wo - 1));
    int y0 = (int)floorf(cy), x0 = (int)floorf(cx);
    int y1 = min(y0 + 1, 19), x1 = min(x0 + 1, 19);
    float wy = cy - (float)y0, wx = cx - (float)x0;

    const float* sp = g_simf + (size_t)bc * HW2;
    float v = (1.f - wy) * ((1.f - wx) * sp[y0 * 20 + x0] + wx * sp[y0 * 20 + x1])
            +         wy * ((1.f - wx) * sp[y1 * 20 + x0] + wx * sp[y1 * 20 + x1]);
    dst[idx] = v;
}

// ---------------------------------------------------------------------------
// Kernel: unified tensor-core conv2 (pre-split bf16, mma.sync.m16n8k16)
// ---------------------------------------------------------------------------
struct LvP {
    const float* pr; const float* w;
    const float* gg; const float* bb; const float* mm; const float* vv;
    const __nv_bfloat16 *xh, *xl, *wh, *wl;
    float* out;
    int C, HW, nt, mt, blk0;
};
struct AllP { LvP lv[3]; };

__device__ __forceinline__ void ldsm4(uint32_t* r, uint32_t a) {
    asm volatile("ldmatrix.sync.aligned.m8n8.x4.shared.b16 {%0,%1,%2,%3},[%4];\n"
        : "=r"(r[0]), "=r"(r[1]), "=r"(r[2]), "=r"(r[3]) : "r"(a));
}
__device__ __forceinline__ void ldsm4t(uint32_t* r, uint32_t a) {
    asm volatile("ldmatrix.sync.aligned.m8n8.x4.trans.shared.b16 {%0,%1,%2,%3},[%4];\n"
        : "=r"(r[0]), "=r"(r[1]), "=r"(r[2]), "=r"(r[3]) : "r"(a));
}
__device__ __forceinline__ void mma16816(float* d, const uint32_t* a,
                                         uint32_t b0, uint32_t b1) {
    asm volatile("mma.sync.aligned.m16n8k16.row.col.f32.bf16.bf16.f32 "
        "{%0,%1,%2,%3},{%4,%5,%6,%7},{%8,%9},{%0,%1,%2,%3};\n"
        : "+f"(d[0]), "+f"(d[1]), "+f"(d[2]), "+f"(d[3])
        : "r"(a[0]), "r"(a[1]), "r"(a[2]), "r"(a[3]), "r"(b0), "r"(b1));
}

__global__ __launch_bounds__(256, 2) void k_conv2t(AllP P)
{
    extern __shared__ char smc[];
    const int OFF_WL = 8192, OFF_XH = 16384, OFF_XL = 32768;
    float* prS  = (float*)(smc + 49152);   // [4][128]
    float* wprS = (float*)(smc + 51200);   // [64][4]

    int bid = blockIdx.x;
    int li  = (bid >= P.lv[1].blk0) + (bid >= P.lv[2].blk0);
    LvP L = P.lv[li];

    int rb     = bid - L.blk0;
    int n_tile = rb % L.nt;
    int r2     = rb / L.nt;
    int m_tile = r2 % L.mt;
    int b      = r2 / L.mt;

    int ptile  = n_tile * 128;
    int K      = L.C + 4;
    int nchunk = L.C >> 6;

    int tid = threadIdx.x;
    int lane = tid & 31, wid = tid >> 5;
    int wm = wid >> 2, wn = wid & 3;

    uint32_t sb = (uint32_t)__cvta_generic_to_shared(smc);

    const __nv_bfloat16* xhb = L.xh + (size_t)b * L.C * L.HW;
    const __nv_bfloat16* xlb = L.xl + (size_t)b * L.C * L.HW;
    const __nv_bfloat16* whb = L.wh + (size_t)m_tile * 64 * L.C;
    const __nv_bfloat16* wlb = L.wl + (size_t)m_tile * 64 * L.C;
    const float* prb = L.pr + (size_t)b * 4 * L.HW;

    for (int i = tid; i < 512; i += 256) {
        int j = i >> 7, n = i & 127;
        int px = ptile + n;
        prS[i] = (px < L.HW) ? prb[(size_t)j * L.HW + px] : 0.f;
    }
    {
        int o = tid >> 2, j = tid & 3;
        wprS[tid] = L.w[(size_t)(m_tile * 64 + o) * K + L.C + j];
    }

    float acc[2][4][4];
#pragma unroll
    for (int i = 0; i < 2; i++)
#pragma unroll
        for (int j = 0; j < 4; j++)
#pragma unroll
            for (int q = 0; q < 4; q++) acc[i][j][q] = 0.f;

    for (int c = 0; c < nchunk; c++) {
        int kbase = c * 64;
#pragma unroll
        for (int it = 0; it < 2; it++) {
            int item = tid + it * 256;
            int o = item >> 3, u = item & 7;
            size_t si = (size_t)o * L.C + kbase + u * 8;
            int off = o * 128 + (((u) ^ (o & 7)) << 4);
            *(uint4*)(smc + off)          = *(const uint4*)(whb + si);
            *(uint4*)(smc + OFF_WL + off) = *(const uint4*)(wlb + si);
        }
#pragma unroll
        for (int it = 0; it < 4; it++) {
            int item = tid + it * 256;
            int kl = item >> 4, u = item & 15;
            int px0 = ptile + u * 8;
            uint4 vh = make_uint4(0, 0, 0, 0), vl = vh;
            if (px0 < L.HW) {
                size_t si = (size_t)(kbase + kl) * L.HW + px0;
                vh = *(const uint4*)(xhb + si);
                vl = *(const uint4*)(xlb + si);
            }
            int off = kl * 256 + (((u) ^ (kl & 7)) << 4);
            *(uint4*)(smc + OFF_XH + off) = vh;
            *(uint4*)(smc + OFF_XL + off) = vl;
        }
        __syncthreads();

#pragma unroll
        for (int ks = 0; ks < 4; ks++) {
            uint32_t ah[2][4], al[2][4];
#pragma unroll
            for (int mi = 0; mi < 2; mi++) {
                int rr = wm * 32 + mi * 16 + (lane & 15);
                int ku = ks * 2 + (lane >> 4);
                uint32_t a = sb + rr * 128 + ((ku ^ (rr & 7)) << 4);
                ldsm4(ah[mi], a);
                ldsm4(al[mi], a + OFF_WL);
            }
            uint32_t bh[2][4], bl[2][4];
#pragma unroll
            for (int g = 0; g < 2; g++) {
                int kr = ks * 16 + (lane & 15);
                int n0 = wn * 32 + g * 16 + ((lane >> 4) * 8);
                uint32_t a = sb + OFF_XH + kr * 256 + (((n0 >> 3) ^ (kr & 7)) << 4);
                ldsm4t(bh[g], a);
                ldsm4t(bl[g], a + (OFF_XL - OFF_XH));
            }
#pragma unroll
            for (int mi = 0; mi < 2; mi++)
#pragma unroll
                for (int g = 0; g < 2; g++)
#pragma unroll
                    for (int t = 0; t < 2; t++) {
                        int ni = g * 2 + t;
                        mma16816(acc[mi][ni], ah[mi], bh[g][2*t], bh[g][2*t + 1]);
                        mma16816(acc[mi][ni], ah[mi], bl[g][2*t], bl[g][2*t + 1]);
                        mma16816(acc[mi][ni], al[mi], bh[g][2*t], bh[g][2*t + 1]);
                    }
        }
        __syncthreads();
    }

    int ro = lane >> 2, co = (lane & 3) * 2;
#pragma unroll
    for (int mi = 0; mi < 2; mi++) {
#pragma unroll
        for (int half = 0; half < 2; half++) {
            int rloc = wm * 32 + mi * 16 + half * 8 + ro;
            int oo = m_tile * 64 + rloc;
            float w0 = wprS[rloc * 4 + 0], w1 = wprS[rloc * 4 + 1];
            float w2 = wprS[rloc * 4 + 2], w3 = wprS[rloc * 4 + 3];
            float sc = L.gg[oo] * rsqrtf(L.vv[oo] + 1e-3f);
            float sh = L.bb[oo] - L.mm[oo] * sc;
            float* ob = L.out + (size_t)(b * L.C + oo) * L.HW;
#pragma unroll
            for (int ni = 0; ni < 4; ni++) {
                int nloc = wn * 32 + ni * 8 + co;
                int px = ptile + nloc;
                if (px < L.HW) {
                    float p0 = acc[mi][ni][half * 2 + 0]
                             + w0 * prS[nloc]       + w1 * prS[128 + nloc]
                             + w2 * prS[256 + nloc] + w3 * prS[384 + nloc];
                    float p1 = acc[mi][ni][half * 2 + 1]
                             + w0 * prS[nloc + 1]       + w1 * prS[128 + nloc + 1]
                             + w2 * prS[256 + nloc + 1] + w3 * prS[384 + nloc + 1];
                    float y0 = p0 * sc + sh;
                    float y1 = p1 * sc + sh;
                    float2 r;
                    r.x = y0 / (1.f + __expf(-y0));
                    r.y = y1 / (1.f + __expf(-y1));
                    *(float2*)(ob + px) = r;
                }
            }
        }
    }
}

// ---------------------------------------------------------------------------
// Launch
// ---------------------------------------------------------------------------
extern "C" void kernel_launch(void* const* d_in, const int* in_sizes, int n_in,
                              void* d_out, int out_size)
{
    const float *f0 = nullptr, *f1 = nullptr, *f2 = nullptr, *w1 = nullptr;
    const float* bn1[4] = {nullptr, nullptr, nullptr, nullptr};
    const float* w2[3]  = {nullptr, nullptr, nullptr};
    const float* bn2[3][4];

    for (int i = 0; i < n_in; i++) {
        int sz = in_sizes[i];
        if (sz == 13107200)      f0 = (const float*)d_in[i];
        else if (sz == 6553600)  f1 = (const float*)d_in[i];
        else if (sz == 3276800)  f2 = (const float*)d_in[i];
        else if (sz == 972) {
            w1 = (const float*)d_in[i];
            for (int j = 0; j < 4; j++) bn1[j] = (const float*)d_in[i + 1 + j];
        } else if (sz == 16896) {
            w2[0] = (const float*)d_in[i];
            for (int j = 0; j < 4; j++) bn2[0][j] = (const float*)d_in[i + 1 + j];
        } else if (sz == 66560) {
            w2[1] = (const float*)d_in[i];
            for (int j = 0; j < 4; j++) bn2[1][j] = (const float*)d_in[i + 1 + j];
        } else if (sz == 264192) {
            w2[2] = (const float*)d_in[i];
            for (int j = 0; j < 4; j++) bn2[2][j] = (const float*)d_in[i + 1 + j];
        }
    }
    if (!f0 || !f1 || !f2 || !w1 || !w2[0] || !w2[1] || !w2[2]) return;

    int sim_smem = (32 * WROWS * CROW + 3 * 32 * 200) * (int)sizeof(float);
    cudaFuncSetAttribute(k_sim, cudaFuncAttributeMaxDynamicSharedMemorySize, sim_smem);
    cudaFuncSetAttribute(k_conv2t, cudaFuncAttributeMaxDynamicSharedMemorySize, 52224);

    void *pr0, *pr1, *simf, *xh, *xl, *wh, *wl;
    cudaGetSymbolAddress(&pr0, g_pr0);
    cudaGetSymbolAddress(&pr1, g_pr1);
    cudaGetSymbolAddress(&simf, g_simf);
    cudaGetSymbolAddress(&xh, g_xh);
    cudaGetSymbolAddress(&xl, g_xl);
    cudaGetSymbolAddress(&wh, g_wh);
    cudaGetSymbolAddress(&wl, g_wl);
    const __nv_bfloat16* XH = (const __nv_bfloat16*)xh;
    const __nv_bfloat16* XL = (const __nv_bfloat16*)xl;
    const __nv_bfloat16* WH = (const __nv_bfloat16*)wh;
    const __nv_bfloat16* WL = (const __nv_bfloat16*)wl;

    float* out0 = (float*)d_out;
    float* out1 = out0 + (size_t)B_ * 128 * 6400;
    float* out2 = out1 + (size_t)B_ * 256 * 1600;

    k_cvt_act<<<1400, 512>>>(f0, f1, f2);
    k_cvt_w<<<168, 256>>>(w2[0], w2[1], w2[2]);
    k_sim<<<dim3(NCH, B_, 2), 256, sim_smem>>>(f2);
    k_reduce<<<380, 256>>>();
    k_softmax1<<<dim3(4, B_), 384>>>(w1, bn1[0], bn1[1], bn1[2], bn1[3]);
    k_resize<<<(B_ * 4 * 6400 + 255) / 256, 256>>>((float*)pr0, 80, 80);
    k_resize<<<(B_ * 4 * 1600 + 255) / 256, 256>>>((float*)pr1, 40, 40);

    AllP P;
    P.lv[0] = { (const float*)pr0, w2[0],
                bn2[0][0], bn2[0][1], bn2[0][2], bn2[0][3],
                XH, XL, WH, WL,
                out0, 128, 6400, 50, 2, 0 };
    P.lv[1] = { (const float*)pr1, w2[1],
                bn2[1][0], bn2[1][1], bn2[1][2], bn2[1][3],
                XH + 3276800, XL + 3276800, WH + 16384, WL + 16384,
                out1, 256, 1600, 13, 4, 400 };
    P.lv[2] = { (const float*)simf, w2[2],
                bn2[2][0], bn2[2][1], bn2[2][2], bn2[2][3],
                XH + 4915200, XL + 4915200, WH + 81920, WL + 81920,
                out2, 512, 400, 4, 8, 608 };
    int total_blocks = 400 + 208 + 128;

    k_conv2t<<<total_blocks, 256, 52224>>>(P);
}

// round 7
// speedup vs baseline: 3.0287x; 1.1414x over previous
#include <cuda_runtime.h>
#include <cuda_bf16.h>
#include <cstdint>

// Sim2: temporal cost-volume + softmax + 1x1convs on a 3-level pyramid.
//   k_cvt_w    : fp32 -> split-bf16 planes of the [C][C] weight blocks
//   k_sim      : cost volume partials, f32x2 packed math, past-in-registers
//   k_reduce   : wide 16-chunk fold -> g_L (full-chip streaming)
//   k_softmax1 : in-register softmax(81) + conv1(243->4) + BN + SiLU
//   k_resize2  : both bilinear upsamples in one launch
//   k_conv2t   : unified 3-level C->C tensor-core GEMM (BM=128, in-kernel
//                fp32->split-bf16 X conversion) + pr-epilogue + BN + SiLU

#define B_    4
#define C2    512
#define HW2   400
#define NS_   81
#define NCH   16
#define WROWS 18
#define CROW  29

__device__ float g_Lpart[NCH * 12 * NS_ * HW2];
__device__ float g_L[12 * NS_ * HW2];
__device__ float g_simf[B_ * 4 * HW2];
__device__ float g_pr0[B_ * 4 * 6400];
__device__ float g_pr1[B_ * 4 * 1600];

// weights [o][k], k<C: lvl0 @0 (16384), lvl1 @16384 (65536), lvl2 @81920 (262144)
__device__ __align__(16) __nv_bfloat16 g_wh[344064];
__device__ __align__(16) __nv_bfloat16 g_wl[344064];

__device__ __forceinline__ void pack8(const float* v, uint4& hi, uint4& lo) {
    uint32_t h[4], l[4];
#pragma unroll
    for (int j = 0; j < 4; j++) {
        __nv_bfloat162 hh = __floats2bfloat162_rn(v[2*j], v[2*j+1]);
        float2 hf = __bfloat1622float2(hh);
        __nv_bfloat162 ll = __floats2bfloat162_rn(v[2*j] - hf.x, v[2*j+1] - hf.y);
        h[j] = *reinterpret_cast<uint32_t*>(&hh);
        l[j] = *reinterpret_cast<uint32_t*>(&ll);
    }
    hi = make_uint4(h[0], h[1], h[2], h[3]);
    lo = make_uint4(l[0], l[1], l[2], l[3]);
}

__device__ __forceinline__ unsigned long long addx2(unsigned long long a,
                                                    unsigned long long b) {
    unsigned long long r;
    asm("add.rn.f32x2 %0, %1, %2;" : "=l"(r) : "l"(a), "l"(b));
    return r;
}
__device__ __forceinline__ unsigned long long packx2(float lo, float hi) {
    unsigned long long r;
    asm("mov.b64 %0, {%1, %2};" : "=l"(r) : "f"(lo), "f"(hi));
    return r;
}

// ---------------------------------------------------------------------------
// Weight conversion: [C][C] blocks. 43008 items x 8. grid = 168 x 256.
// ---------------------------------------------------------------------------
__global__ __launch_bounds__(256) void k_cvt_w(
    const float* __restrict__ w0, const float* __restrict__ w1,
    const float* __restrict__ w2)
{
    int idx = blockIdx.x * 256 + threadIdx.x;
    if (idx >= 43008) return;
    const float* w; size_t dstOff; int C, e;
    if (idx < 2048)       { w = w0; dstOff = 0;     C = 128; e = idx * 8; }
    else if (idx < 10240) { w = w1; dstOff = 16384; C = 256; e = (idx - 2048) * 8; }
    else                  { w = w2; dstOff = 81920; C = 512; e = (idx - 10240) * 8; }
    int o = e / C, k = e - o * C;
    const float* s = w + (size_t)o * (C + 4) + k;
    float v[8];
#pragma unroll
    for (int j = 0; j < 8; j++) v[j] = s[j];
    uint4 hi, lo; pack8(v, hi, lo);
    *(uint4*)(g_wh + dstOff + e) = hi;
    *(uint4*)(g_wl + dstOff + e) = lo;
}

// ---------------------------------------------------------------------------
// Kernel: cost volume partials, f32x2 packed. grid = (NCH, B, 2), 224 thr.
// curS2: channel-pair interleaved padded window [16][WROWS*CROW] (66.8 KB).
// negated past (3t x 16 pairs) lives in registers, loaded straight from gmem.
// ---------------------------------------------------------------------------
__global__ __launch_bounds__(224) void k_sim(const float* __restrict__ f2)
{
    int cc = blockIdx.x;
    int b  = blockIdx.y;
    int h  = blockIdx.z;

    extern __shared__ unsigned long long curS2[];   // [16][522]

    int tid = threadIdx.x;
    int r0  = h * 10;

    const float* curG = f2 + ((size_t)(b * 4 + 3) * C2 + cc * 32) * HW2;

    for (int i = tid; i < 16 * WROWS * 28; i += 224) {
        int c2  = i / (WROWS * 28);
        int rem = i - c2 * (WROWS * 28);
        int wr  = rem / 28, wc = rem - wr * 28;
        int gy  = r0 + wr - 4, gx = wc - 4;
        float lo = 0.f, hi = 0.f;
        if ((unsigned)gy < 20u && (unsigned)gx < 20u) {
            int g = gy * 20 + gx;
            lo = curG[(2 * c2) * HW2 + g];
            hi = curG[(2 * c2 + 1) * HW2 + g];
        }
        curS2[c2 * (WROWS * CROW) + wr * CROW + wc] = packx2(lo, hi);
    }
    __syncthreads();

    if (tid < 200) {
        unsigned long long np[3][16];
#pragma unroll
        for (int t = 0; t < 3; t++) {
            const float* pb = f2 + ((size_t)(b * 4 + t) * C2 + cc * 32) * HW2
                            + r0 * 20 + tid;
#pragma unroll
            for (int c2 = 0; c2 < 16; c2++)
                np[t][c2] = packx2(-pb[(2 * c2) * HW2], -pb[(2 * c2 + 1) * HW2]);
        }

        int lr  = tid / 20;
        int col = tid - lr * 20;
        size_t obase = (((size_t)cc * 12 + b * 3) * NS_) * HW2 + h * 200 + tid;
        const unsigned long long SGN = 0x8000000080000000ULL;

        for (int s = 0; s < NS_; s++) {
            int dy = s / 9, dx = s - dy * 9;
            const unsigned long long* cp =
                curS2 + (lr + dy) * CROW + col + dx;
            unsigned long long a0 = 0ULL, a1 = 0ULL, a2 = 0ULL;
#pragma unroll
            for (int c2 = 0; c2 < 16; c2++) {
                unsigned long long cv = cp[c2 * (WROWS * CROW)];
                unsigned long long d0 = addx2(cv, np[0][c2]);
                unsigned long long d1 = addx2(cv, np[1][c2]);
                unsigned long long d2 = addx2(cv, np[2][c2]);
                a0 = addx2(a0, d0 | SGN);
                a1 = addx2(a1, d1 | SGN);
                a2 = addx2(a2, d2 | SGN);
            }
            float r0f = __uint_as_float((unsigned)a0) + __uint_as_float((unsigned)(a0 >> 32));
            float r1f = __uint_as_float((unsigned)a1) + __uint_as_float((unsigned)(a1 >> 32));
            float r2f = __uint_as_float((unsigned)a2) + __uint_as_float((unsigned)(a2 >> 32));
            size_t o = obase + (size_t)s * HW2;
            g_Lpart[o]                         = r0f;
            g_Lpart[o + (size_t)NS_ * HW2]     = r1f;
            g_Lpart[o + (size_t)2 * NS_ * HW2] = r2f;
        }
    }
}

// ---------------------------------------------------------------------------
// Kernel: wide 16-chunk fold. 97200 float4 outputs. grid = 380 x 256.
// ---------------------------------------------------------------------------
__global__ __launch_bounds__(256) void k_reduce()
{
    int e = blockIdx.x * 256 + threadIdx.x;
    if (e >= 97200) return;
    const float4* src = (const float4*)g_Lpart + e;
    float4 a = src[0];
#pragma unroll
    for (int cc = 1; cc < NCH; cc++) {
        float4 v = src[(size_t)cc * 97200];
        a.x += v.x; a.y += v.y; a.z += v.z; a.w += v.w;
    }
    ((float4*)g_L)[e] = a;
}

// ---------------------------------------------------------------------------
// Kernel: in-register softmax(81) + conv1(243->4) + BN + SiLU.
// grid = (4, B), 384 threads = 3 t-groups x 128 px-lanes (100 active).
// ---------------------------------------------------------------------------
__global__ __launch_bounds__(384) void k_softmax1(
    const float* __restrict__ w1,
    const float* __restrict__ g1, const float* __restrict__ b1,
    const float* __restrict__ m1, const float* __restrict__ v1)
{
    __shared__ float w1s[972];
    __shared__ float opart[12 * 128];

    int b    = blockIdx.y;
    int tid  = threadIdx.x;
    int t    = tid >> 7;
    int lane = tid & 127;
    int px   = blockIdx.x * 100 + lane;

    for (int i = tid; i < 972; i += 384) w1s[i] = w1[i];
    __syncthreads();

    if (lane < 100) {
        const float* Lb = g_L + ((size_t)(b * 3 + t) * NS_) * HW2 + px;
        float e[NS_];
#pragma unroll
        for (int s = 0; s < NS_; s++) e[s] = Lb[(size_t)s * HW2];
        float mx = -1e30f;
#pragma unroll
        for (int s = 0; s < NS_; s++) mx = fmaxf(mx, e[s]);
        float Z = 0.f;
#pragma unroll
        for (int s = 0; s < NS_; s++) { e[s] = __expf(e[s] - mx); Z += e[s]; }
        float rz = 1.f / Z;
        float o0 = 0, o1 = 0, o2 = 0, o3 = 0;
        const float* wt = w1s + t * 81;
#pragma unroll
        for (int s = 0; s < NS_; s++) {
            float p = e[s] * rz;
            o0 += wt[s] * p;       o1 += wt[243 + s] * p;
            o2 += wt[486 + s] * p; o3 += wt[729 + s] * p;
        }
        opart[(t * 4 + 0) * 128 + lane] = o0;
        opart[(t * 4 + 1) * 128 + lane] = o1;
        opart[(t * 4 + 2) * 128 + lane] = o2;
        opart[(t * 4 + 3) * 128 + lane] = o3;
    }
    __syncthreads();

    if (t == 0 && lane < 100) {
#pragma unroll
        for (int oc = 0; oc < 4; oc++) {
            float o = opart[oc * 128 + lane] + opart[(4 + oc) * 128 + lane]
                    + opart[(8 + oc) * 128 + lane];
            float sc = g1[oc] * rsqrtf(v1[oc] + 1e-3f);
            float yv = (o - m1[oc]) * sc + b1[oc];
            g_simf[((size_t)b * 4 + oc) * HW2 + px] = yv / (1.f + __expf(-yv));
        }
    }
}

// ---------------------------------------------------------------------------
// Kernel: both bilinear resizes (align_corners) in one launch. grid=500x256.
// ---------------------------------------------------------------------------
__global__ void k_resize2(float* __restrict__ d0, float* __restrict__ d1)
{
    int idx = blockIdx.x * 256 + threadIdx.x;
    float* dst; int Ho, Wo;
    if (idx < 102400)      { dst = d0; Ho = 80; Wo = 80; }
    else if (idx < 128000) { dst = d1; Ho = 40; Wo = 40; idx -= 102400; }
    else return;

    int xo = idx % Wo;
    int r  = idx / Wo;
    int yo = r % Ho;
    int bc = r / Ho;

    float cy = yo * (19.f / (float)(Ho - 1));
    float cx = xo * (19.f / (float)(Wo - 1));
    int y0 = (int)floorf(cy), x0 = (int)floorf(cx);
    int y1 = min(y0 + 1, 19), x1 = min(x0 + 1, 19);
    float wy = cy - (float)y0, wx = cx - (float)x0;

    const float* sp = g_simf + (size_t)bc * HW2;
    float v = (1.f - wy) * ((1.f - wx) * sp[y0 * 20 + x0] + wx * sp[y0 * 20 + x1])
            +         wy * ((1.f - wx) * sp[y1 * 20 + x0] + wx * sp[y1 * 20 + x1]);
    dst[idx] = v;
}

// ---------------------------------------------------------------------------
// Kernel: unified tensor-core conv2. BM=128 x BN=128, K-chunks of 64,
// 512 threads = 16 warps (4x4), warp tile 32x32. X converted fp32->hi/lo
// bf16 during staging. pr channels + BN + SiLU in fp32 epilogue.
// smem: WH@0 WL@16K XH@32K XL@48K (16KB each) + prS@64K + wprS@66K = 68KB
// ---------------------------------------------------------------------------
struct LvP {
    const float* feat; const float* pr; const float* w;
    const float* gg; const float* bb; const float* mm; const float* vv;
    const __nv_bfloat16 *wh, *wl;
    float* out;
    int C, HW, nt, mt, blk0;
};
struct AllP { LvP lv[3]; };

__device__ __forceinline__ void ldsm4(uint32_t* r, uint32_t a) {
    asm volatile("ldmatrix.sync.aligned.m8n8.x4.shared.b16 {%0,%1,%2,%3},[%4];\n"
        : "=r"(r[0]), "=r"(r[1]), "=r"(r[2]), "=r"(r[3]) : "r"(a));
}
__device__ __forceinline__ void ldsm4t(uint32_t* r, uint32_t a) {
    asm volatile("ldmatrix.sync.aligned.m8n8.x4.trans.shared.b16 {%0,%1,%2,%3},[%4];\n"
        : "=r"(r[0]), "=r"(r[1]), "=r"(r[2]), "=r"(r[3]) : "r"(a));
}
__device__ __forceinline__ void mma16816(float* d, const uint32_t* a,
                                         uint32_t b0, uint32_t b1) {
    asm volatile("mma.sync.aligned.m16n8k16.row.col.f32.bf16.bf16.f32 "
        "{%0,%1,%2,%3},{%4,%5,%6,%7},{%8,%9},{%0,%1,%2,%3};\n"
        : "+f"(d[0]), "+f"(d[1]), "+f"(d[2]), "+f"(d[3])
        : "r"(a[0]), "r"(a[1]), "r"(a[2]), "r"(a[3]), "r"(b0), "r"(b1));
}

__global__ __launch_bounds__(512, 1) void k_conv2t(AllP P)
{
    extern __shared__ char smc[];
    const int OFF_WL = 16384, OFF_XH = 32768, OFF_XL = 49152;
    float* prS  = (float*)(smc + 65536);   // [4][128]
    float* wprS = (float*)(smc + 67584);   // [128][4]

    int bid = blockIdx.x;
    int li  = (bid >= P.lv[1].blk0) + (bid >= P.lv[2].blk0);
    LvP L = P.lv[li];

    int rb     = bid - L.blk0;
    int n_tile = rb % L.nt;
    int r2     = rb / L.nt;
    int m_tile = r2 % L.mt;
    int b      = r2 / L.mt;

    int ptile  = n_tile * 128;
    int K      = L.C + 4;
    int nchunk = L.C >> 6;

    int tid = threadIdx.x;
    int lane = tid & 31, wid = tid >> 5;
    int wm = wid >> 2, wn = wid & 3;

    uint32_t sb = (uint32_t)__cvta_generic_to_shared(smc);

    const float* xbase = L.feat + (size_t)(b * 4 + 3) * L.C * L.HW;
    const __nv_bfloat16* whb = L.wh + (size_t)m_tile * 128 * L.C;
    const __nv_bfloat16* wlb = L.wl + (size_t)m_tile * 128 * L.C;
    const float* prb = L.pr + (size_t)b * 4 * L.HW;

    {
        int j = tid >> 7, n = tid & 127;
        int px = ptile + n;
        prS[tid & 511] = 0.f;  // placeholder; real fill below
        if (tid < 512) {
            prS[j * 128 + n] = (px < L.HW) ? prb[(size_t)j * L.HW + px] : 0.f;
        }
        int o = tid >> 2, jj = tid & 3;
        wprS[tid] = L.w[(size_t)(m_tile * 128 + o) * K + L.C + jj];
    }

    float acc[2][4][4];
#pragma unroll
    for (int i = 0; i < 2; i++)
#pragma unroll
        for (int j = 0; j < 4; j++)
#pragma unroll
            for (int q = 0; q < 4; q++) acc[i][j][q] = 0.f;

    for (int c = 0; c < nchunk; c++) {
        int kbase = c * 64;
        // weights: 1024 16B-units per plane, 2 iters
#pragma unroll
        for (int it = 0; it < 2; it++) {
            int item = tid + it * 512;
            int o = item >> 3, u = item & 7;
            size_t si = (size_t)o * L.C + kbase + u * 8;
            int off = o * 128 + ((u ^ (o & 7)) << 4);
            *(uint4*)(smc + off)          = *(const uint4*)(whb + si);
            *(uint4*)(smc + OFF_WL + off) = *(const uint4*)(wlb + si);
        }
        // activations: 1024 groups of 8 fp32 -> hi/lo bf16, 2 iters
#pragma unroll
        for (int it = 0; it < 2; it++) {
            int item = tid + it * 512;
            int kl = item >> 4, u = item & 15;
            int px0 = ptile + u * 8;
            float v[8] = {0.f, 0.f, 0.f, 0.f, 0.f, 0.f, 0.f, 0.f};
            if (px0 < L.HW) {
                const float* src = xbase + (size_t)(kbase + kl) * L.HW + px0;
                *(float4*)v       = *(const float4*)src;
                *(float4*)(v + 4) = *(const float4*)(src + 4);
            }
            uint4 hi, lo; pack8(v, hi, lo);
            int off = kl * 256 + ((u ^ (kl & 7)) << 4);
            *(uint4*)(smc + OFF_XH + off) = hi;
            *(uint4*)(smc + OFF_XL + off) = lo;
        }
        __syncthreads();

#pragma unroll
        for (int ks = 0; ks < 4; ks++) {
            uint32_t ah[2][4], al[2][4];
#pragma unroll
            for (int mi = 0; mi < 2; mi++) {
                int rr = wm * 32 + mi * 16 + (lane & 15);
                int ku = ks * 2 + (lane >> 4);
                uint32_t a = sb + rr * 128 + ((ku ^ (rr & 7)) << 4);
                ldsm4(ah[mi], a);
                ldsm4(al[mi], a + OFF_WL);
            }
            uint32_t bh[2][4], bl[2][4];
#pragma unroll
            for (int g = 0; g < 2; g++) {
                int kr = ks * 16 + (lane & 15);
                int n0 = wn * 32 + g * 16 + ((lane >> 4) * 8);
                uint32_t a = sb + OFF_XH + kr * 256 + (((n0 >> 3) ^ (kr & 7)) << 4);
                ldsm4t(bh[g], a);
                ldsm4t(bl[g], a + (OFF_XL - OFF_XH));
            }
#pragma unroll
            for (int mi = 0; mi < 2; mi++)
#pragma unroll
                for (int g = 0; g < 2; g++)
#pragma unroll
                    for (int t = 0; t < 2; t++) {
                        int ni = g * 2 + t;
                        mma16816(acc[mi][ni], ah[mi], bh[g][2*t], bh[g][2*t + 1]);
                        mma16816(acc[mi][ni], ah[mi], bl[g][2*t], bl[g][2*t + 1]);
                        mma16816(acc[mi][ni], al[mi], bh[g][2*t], bh[g][2*t + 1]);
                    }
        }
        __syncthreads();
    }

    int ro = lane >> 2, co = (lane & 3) * 2;
#pragma unroll
    for (int mi = 0; mi < 2; mi++) {
#pragma unroll
        for (int half = 0; half < 2; half++) {
            int rloc = wm * 32 + mi * 16 + half * 8 + ro;
            int oo = m_tile * 128 + rloc;
            float w0 = wprS[rloc * 4 + 0], w1 = wprS[rloc * 4 + 1];
            float w2 = wprS[rloc * 4 + 2], w3 = wprS[rloc * 4 + 3];
            float sc = L.gg[oo] * rsqrtf(L.vv[oo] + 1e-3f);
            float sh = L.bb[oo] - L.mm[oo] * sc;
            float* ob = L.out + (size_t)(b * L.C + oo) * L.HW;
#pragma unroll
            for (int ni = 0; ni < 4; ni++) {
                int nloc = wn * 32 + ni * 8 + co;
                int px = ptile + nloc;
                if (px < L.HW) {
                    float p0 = acc[mi][ni][half * 2 + 0]
                             + w0 * prS[nloc]       + w1 * prS[128 + nloc]
                             + w2 * prS[256 + nloc] + w3 * prS[384 + nloc];
                    float p1 = acc[mi][ni][half * 2 + 1]
                             + w0 * prS[nloc + 1]       + w1 * prS[128 + nloc + 1]
                             + w2 * prS[256 + nloc + 1] + w3 * prS[384 + nloc + 1];
                    float y0 = p0 * sc + sh;
                    float y1 = p1 * sc + sh;
                    float2 r;
                    r.x = y0 / (1.f + __expf(-y0));
                    r.y = y1 / (1.f + __expf(-y1));
                    *(float2*)(ob + px) = r;
                }
            }
        }
    }
}

// ---------------------------------------------------------------------------
// Launch
// ---------------------------------------------------------------------------
extern "C" void kernel_launch(void* const* d_in, const int* in_sizes, int n_in,
                              void* d_out, int out_size)
{
    const float *f0 = nullptr, *f1 = nullptr, *f2 = nullptr, *w1 = nullptr;
    const float* bn1[4] = {nullptr, nullptr, nullptr, nullptr};
    const float* w2[3]  = {nullptr, nullptr, nullptr};
    const float* bn2[3][4];

    for (int i = 0; i < n_in; i++) {
        int sz = in_sizes[i];
        if (sz == 13107200)      f0 = (const float*)d_in[i];
        else if (sz == 6553600)  f1 = (const float*)d_in[i];
        else if (sz == 3276800)  f2 = (const float*)d_in[i];
        else if (sz == 972) {
            w1 = (const float*)d_in[i];
            for (int j = 0; j < 4; j++) bn1[j] = (const float*)d_in[i + 1 + j];
        } else if (sz == 16896) {
            w2[0] = (const float*)d_in[i];
            for (int j = 0; j < 4; j++) bn2[0][j] = (const float*)d_in[i + 1 + j];
        } else if (sz == 66560) {
            w2[1] = (const float*)d_in[i];
            for (int j = 0; j < 4; j++) bn2[1][j] = (const float*)d_in[i + 1 + j];
        } else if (sz == 264192) {
            w2[2] = (const float*)d_in[i];
            for (int j = 0; j < 4; j++) bn2[2][j] = (const float*)d_in[i + 1 + j];
        }
    }
    if (!f0 || !f1 || !f2 || !w1 || !w2[0] || !w2[1] || !w2[2]) return;

    int sim_smem = 16 * WROWS * CROW * 8;          // 66816 B
    cudaFuncSetAttribute(k_sim, cudaFuncAttributeMaxDynamicSharedMemorySize, sim_smem);
    cudaFuncSetAttribute(k_conv2t, cudaFuncAttributeMaxDynamicSharedMemorySize, 69632);

    void *pr0, *pr1, *wh, *wl;
    cudaGetSymbolAddress(&pr0, g_pr0);
    cudaGetSymbolAddress(&pr1, g_pr1);
    cudaGetSymbolAddress(&wh, g_wh);
    cudaGetSymbolAddress(&wl, g_wl);
    void* simf;
    cudaGetSymbolAddress(&simf, g_simf);
    const __nv_bfloat16* WH = (const __nv_bfloat16*)wh;
    const __nv_bfloat16* WL = (const __nv_bfloat16*)wl;

    float* out0 = (float*)d_out;
    float* out1 = out0 + (size_t)B_ * 128 * 6400;
    float* out2 = out1 + (size_t)B_ * 256 * 1600;

    k_cvt_w<<<168, 256>>>(w2[0], w2[1], w2[2]);
    k_sim<<<dim3(NCH, B_, 2), 224, sim_smem>>>(f2);
    k_reduce<<<380, 256>>>();
    k_softmax1<<<dim3(4, B_), 384>>>(w1, bn1[0], bn1[1], bn1[2], bn1[3]);
    k_resize2<<<500, 256>>>((float*)pr0, (float*)pr1);

    AllP P;
    P.lv[0] = { f0, (const float*)pr0, w2[0],
                bn2[0][0], bn2[0][1], bn2[0][2], bn2[0][3],
                WH, WL,
                out0, 128, 6400, 50, 1, 0 };
    P.lv[1] = { f1, (const float*)pr1, w2[1],
                bn2[1][0], bn2[1][1], bn2[1][2], bn2[1][3],
                WH + 16384, WL + 16384,
                out1, 256, 1600, 13, 2, 200 };
    P.lv[2] = { f2, (const float*)simf, w2[2],
                bn2[2][0], bn2[2][1], bn2[2][2], bn2[2][3],
                WH + 81920, WL + 81920,
                out2, 512, 400, 4, 4, 304 };
    int total_blocks = 200 + 104 + 64;   // 368

    k_conv2t<<<total_blocks, 512, 69632>>>(P);
}

// round 8
// speedup vs baseline: 3.3262x; 1.0982x over previous
#include <cuda_runtime.h>
#include <cuda_bf16.h>
#include <cstdint>

// Sim2: temporal cost-volume + softmax + 1x1convs on a 3-level pyramid.
//   k_cvt_w    : fp32 -> split-bf16 planes of the [C][C] weight blocks
//   k_sim      : cost volume partials, f32x2 packed math, past-in-registers
//   k_reduce   : wide 16-chunk fold -> g_L
//   k_softmax1 : in-register softmax(81) + conv1 + BN + SiLU (64 blocks)
//   k_resize2  : both bilinear upsamples in one launch
//   k_conv2t   : unified 3-level C->C tensor-core GEMM, 256thr/occ2,
//                heavy-blocks-first, in-kernel X split + pr/BN/SiLU epilogue

#define B_    4
#define C2    512
#define HW2   400
#define NS_   81
#define NCH   16
#define WROWS 18
#define CROW  29

__device__ float g_Lpart[NCH * 12 * NS_ * HW2];
__device__ float g_L[12 * NS_ * HW2];
__device__ float g_simf[B_ * 4 * HW2];
__device__ float g_pr0[B_ * 4 * 6400];
__device__ float g_pr1[B_ * 4 * 1600];

// weights [o][k], k<C: lvl0 @0 (16384), lvl1 @16384 (65536), lvl2 @81920 (262144)
__device__ __align__(16) __nv_bfloat16 g_wh[344064];
__device__ __align__(16) __nv_bfloat16 g_wl[344064];

__device__ __forceinline__ void pack8(const float* v, uint4& hi, uint4& lo) {
    uint32_t h[4], l[4];
#pragma unroll
    for (int j = 0; j < 4; j++) {
        __nv_bfloat162 hh = __floats2bfloat162_rn(v[2*j], v[2*j+1]);
        float2 hf = __bfloat1622float2(hh);
        __nv_bfloat162 ll = __floats2bfloat162_rn(v[2*j] - hf.x, v[2*j+1] - hf.y);
        h[j] = *reinterpret_cast<uint32_t*>(&hh);
        l[j] = *reinterpret_cast<uint32_t*>(&ll);
    }
    hi = make_uint4(h[0], h[1], h[2], h[3]);
    lo = make_uint4(l[0], l[1], l[2], l[3]);
}

__device__ __forceinline__ unsigned long long addx2(unsigned long long a,
                                                    unsigned long long b) {
    unsigned long long r;
    asm("add.rn.f32x2 %0, %1, %2;" : "=l"(r) : "l"(a), "l"(b));
    return r;
}
__device__ __forceinline__ unsigned long long packx2(float lo, float hi) {
    unsigned long long r;
    asm("mov.b64 %0, {%1, %2};" : "=l"(r) : "f"(lo), "f"(hi));
    return r;
}

// ---------------------------------------------------------------------------
// Weight conversion: [C][C] blocks. 43008 items x 8. grid = 168 x 256.
// ---------------------------------------------------------------------------
__global__ __launch_bounds__(256) void k_cvt_w(
    const float* __restrict__ w0, const float* __restrict__ w1,
    const float* __restrict__ w2)
{
    int idx = blockIdx.x * 256 + threadIdx.x;
    if (idx >= 43008) return;
    const float* w; size_t dstOff; int C, e;
    if (idx < 2048)       { w = w0; dstOff = 0;     C = 128; e = idx * 8; }
    else if (idx < 10240) { w = w1; dstOff = 16384; C = 256; e = (idx - 2048) * 8; }
    else                  { w = w2; dstOff = 81920; C = 512; e = (idx - 10240) * 8; }
    int o = e / C, k = e - o * C;
    const float* s = w + (size_t)o * (C + 4) + k;
    float v[8];
#pragma unroll
    for (int j = 0; j < 8; j++) v[j] = s[j];
    uint4 hi, lo; pack8(v, hi, lo);
    *(uint4*)(g_wh + dstOff + e) = hi;
    *(uint4*)(g_wl + dstOff + e) = lo;
}

// ---------------------------------------------------------------------------
// Kernel: cost volume partials, f32x2 packed. grid = (NCH, B, 2), 224 thr.
// ---------------------------------------------------------------------------
__global__ __launch_bounds__(224) void k_sim(const float* __restrict__ f2)
{
    int cc = blockIdx.x;
    int b  = blockIdx.y;
    int h  = blockIdx.z;

    extern __shared__ unsigned long long curS2[];   // [16][WROWS*CROW]

    int tid = threadIdx.x;
    int r0  = h * 10;

    const float* curG = f2 + ((size_t)(b * 4 + 3) * C2 + cc * 32) * HW2;

    for (int i = tid; i < 16 * WROWS * 28; i += 224) {
        int c2  = i / (WROWS * 28);
        int rem = i - c2 * (WROWS * 28);
        int wr  = rem / 28, wc = rem - wr * 28;
        int gy  = r0 + wr - 4, gx = wc - 4;
        float lo = 0.f, hi = 0.f;
        if ((unsigned)gy < 20u && (unsigned)gx < 20u) {
            int g = gy * 20 + gx;
            lo = curG[(2 * c2) * HW2 + g];
            hi = curG[(2 * c2 + 1) * HW2 + g];
        }
        curS2[c2 * (WROWS * CROW) + wr * CROW + wc] = packx2(lo, hi);
    }
    __syncthreads();

    if (tid < 200) {
        unsigned long long np[3][16];
#pragma unroll
        for (int t = 0; t < 3; t++) {
            const float* pb = f2 + ((size_t)(b * 4 + t) * C2 + cc * 32) * HW2
                            + r0 * 20 + tid;
#pragma unroll
            for (int c2 = 0; c2 < 16; c2++)
                np[t][c2] = packx2(-pb[(2 * c2) * HW2], -pb[(2 * c2 + 1) * HW2]);
        }

        int lr  = tid / 20;
        int col = tid - lr * 20;
        size_t obase = (((size_t)cc * 12 + b * 3) * NS_) * HW2 + h * 200 + tid;
        const unsigned long long SGN = 0x8000000080000000ULL;

        for (int s = 0; s < NS_; s++) {
            int dy = s / 9, dx = s - dy * 9;
            const unsigned long long* cp =
                curS2 + (lr + dy) * CROW + col + dx;
            unsigned long long a0 = 0ULL, a1 = 0ULL, a2 = 0ULL;
#pragma unroll
            for (int c2 = 0; c2 < 16; c2++) {
                unsigned long long cv = cp[c2 * (WROWS * CROW)];
                unsigned long long d0 = addx2(cv, np[0][c2]);
                unsigned long long d1 = addx2(cv, np[1][c2]);
                unsigned long long d2 = addx2(cv, np[2][c2]);
                a0 = addx2(a0, d0 | SGN);
                a1 = addx2(a1, d1 | SGN);
                a2 = addx2(a2, d2 | SGN);
            }
            float r0f = __uint_as_float((unsigned)a0) + __uint_as_float((unsigned)(a0 >> 32));
            float r1f = __uint_as_float((unsigned)a1) + __uint_as_float((unsigned)(a1 >> 32));
            float r2f = __uint_as_float((unsigned)a2) + __uint_as_float((unsigned)(a2 >> 32));
            size_t o = obase + (size_t)s * HW2;
            g_Lpart[o]                         = r0f;
            g_Lpart[o + (size_t)NS_ * HW2]     = r1f;
            g_Lpart[o + (size_t)2 * NS_ * HW2] = r2f;
        }
    }
}

// ---------------------------------------------------------------------------
// Kernel: wide 16-chunk fold. 97200 float4 outputs. grid = 380 x 256.
// ---------------------------------------------------------------------------
__global__ __launch_bounds__(256) void k_reduce()
{
    int e = blockIdx.x * 256 + threadIdx.x;
    if (e >= 97200) return;
    const float4* src = (const float4*)g_Lpart + e;
    float4 a = src[0];
#pragma unroll
    for (int cc = 1; cc < NCH; cc++) {
        float4 v = src[(size_t)cc * 97200];
        a.x += v.x; a.y += v.y; a.z += v.z; a.w += v.w;
    }
    ((float4*)g_L)[e] = a;
}

// ---------------------------------------------------------------------------
// Kernel: in-register softmax(81) + conv1(243->4) + BN + SiLU.
// grid = (16, B) = 64 blocks, 96 threads = 3 t-groups x 32 lanes (25 px each).
// ---------------------------------------------------------------------------
__global__ __launch_bounds__(96) void k_softmax1(
    const float* __restrict__ w1,
    const float* __restrict__ g1, const float* __restrict__ b1,
    const float* __restrict__ m1, const float* __restrict__ v1)
{
    __shared__ float w1s[972];
    __shared__ float opart[12 * 32];

    int b    = blockIdx.y;
    int tid  = threadIdx.x;
    int t    = tid >> 5;
    int lane = tid & 31;
    int px   = blockIdx.x * 25 + lane;

    for (int i = tid; i < 972; i += 96) w1s[i] = w1[i];
    __syncthreads();

    if (lane < 25) {
        const float* Lb = g_L + ((size_t)(b * 3 + t) * NS_) * HW2 + px;
        float e[NS_];
#pragma unroll
        for (int s = 0; s < NS_; s++) e[s] = Lb[(size_t)s * HW2];
        float mx = -1e30f;
#pragma unroll
        for (int s = 0; s < NS_; s++) mx = fmaxf(mx, e[s]);
        float Z = 0.f;
#pragma unroll
        for (int s = 0; s < NS_; s++) { e[s] = __expf(e[s] - mx); Z += e[s]; }
        float rz = 1.f / Z;
        float o0 = 0, o1 = 0, o2 = 0, o3 = 0;
        const float* wt = w1s + t * 81;
#pragma unroll
        for (int s = 0; s < NS_; s++) {
            float p = e[s] * rz;
            o0 += wt[s] * p;       o1 += wt[243 + s] * p;
            o2 += wt[486 + s] * p; o3 += wt[729 + s] * p;
        }
        opart[(t * 4 + 0) * 32 + lane] = o0;
        opart[(t * 4 + 1) * 32 + lane] = o1;
        opart[(t * 4 + 2) * 32 + lane] = o2;
        opart[(t * 4 + 3) * 32 + lane] = o3;
    }
    __syncthreads();

    if (t == 0 && lane < 25) {
#pragma unroll
        for (int oc = 0; oc < 4; oc++) {
            float o = opart[oc * 32 + lane] + opart[(4 + oc) * 32 + lane]
                    + opart[(8 + oc) * 32 + lane];
            float sc = g1[oc] * rsqrtf(v1[oc] + 1e-3f);
            float yv = (o - m1[oc]) * sc + b1[oc];
            g_simf[((size_t)b * 4 + oc) * HW2 + px] = yv / (1.f + __expf(-yv));
        }
    }
}

// ---------------------------------------------------------------------------
// Kernel: both bilinear resizes (align_corners) in one launch. grid=500x256.
// ---------------------------------------------------------------------------
__global__ void k_resize2(float* __restrict__ d0, float* __restrict__ d1)
{
    int idx = blockIdx.x * 256 + threadIdx.x;
    float* dst; int Ho, Wo;
    if (idx < 102400)      { dst = d0; Ho = 80; Wo = 80; }
    else if (idx < 128000) { dst = d1; Ho = 40; Wo = 40; idx -= 102400; }
    else return;

    int xo = idx % Wo;
    int r  = idx / Wo;
    int yo = r % Ho;
    int bc = r / Ho;

    float cy = yo * (19.f / (float)(Ho - 1));
    float cx = xo * (19.f / (float)(Wo - 1));
    int y0 = (int)floorf(cy), x0 = (int)floorf(cx);
    int y1 = min(y0 + 1, 19), x1 = min(x0 + 1, 19);
    float wy = cy - (float)y0, wx = cx - (float)x0;

    const float* sp = g_simf + (size_t)bc * HW2;
    float v = (1.f - wy) * ((1.f - wx) * sp[y0 * 20 + x0] + wx * sp[y0 * 20 + x1])
            +         wy * ((1.f - wx) * sp[y1 * 20 + x0] + wx * sp[y1 * 20 + x1]);
    dst[idx] = v;
}

// ---------------------------------------------------------------------------
// Kernel: unified tensor-core conv2. BM=64 x BN=128, 256 threads (8 warps,
// 2x4), occupancy 2 for staging/MMA overlap. X converted fp32->hi/lo bf16
// during staging; W from pre-split planes. Heavy levels scheduled first.
// smem: WH@0 WL@8K XH@16K XL@32K + prS@48K + wprS@50K = 51.2KB
// ---------------------------------------------------------------------------
struct LvP {
    const float* feat; const float* pr; const float* w;
    const float* gg; const float* bb; const float* mm; const float* vv;
    const __nv_bfloat16 *wh, *wl;
    float* out;
    int C, HW, nt, mt, blk0;
};
struct AllP { LvP lv[3]; };   // lv[0]=level2(heavy), lv[1]=level1, lv[2]=level0

__device__ __forceinline__ void ldsm4(uint32_t* r, uint32_t a) {
    asm volatile("ldmatrix.sync.aligned.m8n8.x4.shared.b16 {%0,%1,%2,%3},[%4];\n"
        : "=r"(r[0]), "=r"(r[1]), "=r"(r[2]), "=r"(r[3]) : "r"(a));
}
__device__ __forceinline__ void ldsm4t(uint32_t* r, uint32_t a) {
    asm volatile("ldmatrix.sync.aligned.m8n8.x4.trans.shared.b16 {%0,%1,%2,%3},[%4];\n"
        : "=r"(r[0]), "=r"(r[1]), "=r"(r[2]), "=r"(r[3]) : "r"(a));
}
__device__ __forceinline__ void mma16816(float* d, const uint32_t* a,
                                         uint32_t b0, uint32_t b1) {
    asm volatile("mma.sync.aligned.m16n8k16.row.col.f32.bf16.bf16.f32 "
        "{%0,%1,%2,%3},{%4,%5,%6,%7},{%8,%9},{%0,%1,%2,%3};\n"
        : "+f"(d[0]), "+f"(d[1]), "+f"(d[2]), "+f"(d[3])
        : "r"(a[0]), "r"(a[1]), "r"(a[2]), "r"(a[3]), "r"(b0), "r"(b1));
}

__global__ __launch_bounds__(256, 2) void k_conv2t(AllP P)
{
    extern __shared__ char smc[];
    const int OFF_WL = 8192, OFF_XH = 16384, OFF_XL = 32768;
    float* prS  = (float*)(smc + 49152);   // [4][128]
    float* wprS = (float*)(smc + 51200);   // [64][4]

    int bid = blockIdx.x;
    int li  = (bid >= P.lv[1].blk0) + (bid >= P.lv[2].blk0);
    LvP L = P.lv[li];

    int rb     = bid - L.blk0;
    int n_tile = rb % L.nt;
    int r2     = rb / L.nt;
    int m_tile = r2 % L.mt;
    int b      = r2 / L.mt;

    int ptile  = n_tile * 128;
    int K      = L.C + 4;
    int nchunk = L.C >> 6;

    int tid = threadIdx.x;
    int lane = tid & 31, wid = tid >> 5;
    int wm = wid >> 2, wn = wid & 3;

    uint32_t sb = (uint32_t)__cvta_generic_to_shared(smc);

    const float* xbase = L.feat + (size_t)(b * 4 + 3) * L.C * L.HW;
    const __nv_bfloat16* whb = L.wh + (size_t)m_tile * 64 * L.C;
    const __nv_bfloat16* wlb = L.wl + (size_t)m_tile * 64 * L.C;
    const float* prb = L.pr + (size_t)b * 4 * L.HW;

    for (int i = tid; i < 512; i += 256) {
        int j = i >> 7, n = i & 127;
        int px = ptile + n;
        prS[i] = (px < L.HW) ? prb[(size_t)j * L.HW + px] : 0.f;
    }
    {
        int o = tid >> 2, jj = tid & 3;
        wprS[tid] = L.w[(size_t)(m_tile * 64 + o) * K + L.C + jj];
    }

    float acc[2][4][4];
#pragma unroll
    for (int i = 0; i < 2; i++)
#pragma unroll
        for (int j = 0; j < 4; j++)
#pragma unroll
            for (int q = 0; q < 4; q++) acc[i][j][q] = 0.f;

    for (int c = 0; c < nchunk; c++) {
        int kbase = c * 64;
        // weights: 512 16B-units per plane (2 iters)
#pragma unroll
        for (int it = 0; it < 2; it++) {
            int item = tid + it * 256;
            int o = item >> 3, u = item & 7;
            size_t si = (size_t)o * L.C + kbase + u * 8;
            int off = o * 128 + ((u ^ (o & 7)) << 4);
            *(uint4*)(smc + off)          = *(const uint4*)(whb + si);
            *(uint4*)(smc + OFF_WL + off) = *(const uint4*)(wlb + si);
        }
        // activations: 1024 groups of 8 fp32 -> hi/lo bf16 (4 iters)
#pragma unroll
        for (int it = 0; it < 4; it++) {
            int item = tid + it * 256;
            int kl = item >> 4, u = item & 15;
            int px0 = ptile + u * 8;
            float v[8] = {0.f, 0.f, 0.f, 0.f, 0.f, 0.f, 0.f, 0.f};
            if (px0 < L.HW) {
                const float* src = xbase + (size_t)(kbase + kl) * L.HW + px0;
                *(float4*)v       = *(const float4*)src;
                *(float4*)(v + 4) = *(const float4*)(src + 4);
            }
            uint4 hi, lo; pack8(v, hi, lo);
            int off = kl * 256 + ((u ^ (kl & 7)) << 4);
            *(uint4*)(smc + OFF_XH + off) = hi;
            *(uint4*)(smc + OFF_XL + off) = lo;
        }
        __syncthreads();

#pragma unroll
        for (int ks = 0; ks < 4; ks++) {
            uint32_t ah[2][4], al[2][4];
#pragma unroll
            for (int mi = 0; mi < 2; mi++) {
                int rr = wm * 32 + mi * 16 + (lane & 15);
                int ku = ks * 2 + (lane >> 4);
                uint32_t a = sb + rr * 128 + ((ku ^ (rr & 7)) << 4);
                ldsm4(ah[mi], a);
                ldsm4(al[mi], a + OFF_WL);
            }
            uint32_t bh[2][4], bl[2][4];
#pragma unroll
            for (int g = 0; g < 2; g++) {
                int kr = ks * 16 + (lane & 15);
                int n0 = wn * 32 + g * 16 + ((lane >> 4) * 8);
                uint32_t a = sb + OFF_XH + kr * 256 + (((n0 >> 3) ^ (kr & 7)) << 4);
                ldsm4t(bh[g], a);
                ldsm4t(bl[g], a + (OFF_XL - OFF_XH));
            }
#pragma unroll
            for (int mi = 0; mi < 2; mi++)
#pragma unroll
                for (int g = 0; g < 2; g++)
#pragma unroll
                    for (int t = 0; t < 2; t++) {
                        int ni = g * 2 + t;
                        mma16816(acc[mi][ni], ah[mi], bh[g][2*t], bh[g][2*t + 1]);
                        mma16816(acc[mi][ni], ah[mi], bl[g][2*t], bl[g][2*t + 1]);
                        mma16816(acc[mi][ni], al[mi], bh[g][2*t], bh[g][2*t + 1]);
                    }
        }
        __syncthreads();
    }

    int ro = lane >> 2, co = (lane & 3) * 2;
#pragma unroll
    for (int mi = 0; mi < 2; mi++) {
#pragma unroll
        for (int half = 0; half < 2; half++) {
            int rloc = wm * 32 + mi * 16 + half * 8 + ro;
            int oo = m_tile * 64 + rloc;
            float w0 = wprS[rloc * 4 + 0], w1 = wprS[rloc * 4 + 1];
            float w2 = wprS[rloc * 4 + 2], w3 = wprS[rloc * 4 + 3];
            float sc = L.gg[oo] * rsqrtf(L.vv[oo] + 1e-3f);
            float sh = L.bb[oo] - L.mm[oo] * sc;
            float* ob = L.out + (size_t)(b * L.C + oo) * L.HW;
#pragma unroll
            for (int ni = 0; ni < 4; ni++) {
                int nloc = wn * 32 + ni * 8 + co;
                int px = ptile + nloc;
                if (px < L.HW) {
                    float p0 = acc[mi][ni][half * 2 + 0]
                             + w0 * prS[nloc]       + w1 * prS[128 + nloc]
                             + w2 * prS[256 + nloc] + w3 * prS[384 + nloc];
                    float p1 = acc[mi][ni][half * 2 + 1]
                             + w0 * prS[nloc + 1]       + w1 * prS[128 + nloc + 1]
                             + w2 * prS[256 + nloc + 1] + w3 * prS[384 + nloc + 1];
                    float y0 = p0 * sc + sh;
                    float y1 = p1 * sc + sh;
                    float2 r;
                    r.x = y0 / (1.f + __expf(-y0));
                    r.y = y1 / (1.f + __expf(-y1));
                    *(float2*)(ob + px) = r;
                }
            }
        }
    }
}

// ---------------------------------------------------------------------------
// Launch
// ---------------------------------------------------------------------------
extern "C" void kernel_launch(void* const* d_in, const int* in_sizes, int n_in,
                              void* d_out, int out_size)
{
    const float *f0 = nullptr, *f1 = nullptr, *f2 = nullptr, *w1 = nullptr;
    const float* bn1[4] = {nullptr, nullptr, nullptr, nullptr};
    const float* w2[3]  = {nullptr, nullptr, nullptr};
    const float* bn2[3][4];

    for (int i = 0; i < n_in; i++) {
        int sz = in_sizes[i];
        if (sz == 13107200)      f0 = (const float*)d_in[i];
        else if (sz == 6553600)  f1 = (const float*)d_in[i];
        else if (sz == 3276800)  f2 = (const float*)d_in[i];
        else if (sz == 972) {
            w1 = (const float*)d_in[i];
            for (int j = 0; j < 4; j++) bn1[j] = (const float*)d_in[i + 1 + j];
        } else if (sz == 16896) {
            w2[0] = (const float*)d_in[i];
            for (int j = 0; j < 4; j++) bn2[0][j] = (const float*)d_in[i + 1 + j];
        } else if (sz == 66560) {
            w2[1] = (const float*)d_in[i];
            for (int j = 0; j < 4; j++) bn2[1][j] = (const float*)d_in[i + 1 + j];
        } else if (sz == 264192) {
            w2[2] = (const float*)d_in[i];
            for (int j = 0; j < 4; j++) bn2[2][j] = (const float*)d_in[i + 1 + j];
        }
    }
    if (!f0 || !f1 || !f2 || !w1 || !w2[0] || !w2[1] || !w2[2]) return;

    int sim_smem = 16 * WROWS * CROW * 8;          // 66816 B
    cudaFuncSetAttribute(k_sim, cudaFuncAttributeMaxDynamicSharedMemorySize, sim_smem);
    cudaFuncSetAttribute(k_conv2t, cudaFuncAttributeMaxDynamicSharedMemorySize, 52224);

    void *pr0, *pr1, *wh, *wl, *simf;
    cudaGetSymbolAddress(&pr0, g_pr0);
    cudaGetSymbolAddress(&pr1, g_pr1);
    cudaGetSymbolAddress(&wh, g_wh);
    cudaGetSymbolAddress(&wl, g_wl);
    cudaGetSymbolAddress(&simf, g_simf);
    const __nv_bfloat16* WH = (const __nv_bfloat16*)wh;
    const __nv_bfloat16* WL = (const __nv_bfloat16*)wl;

    float* out0 = (float*)d_out;
    float* out1 = out0 + (size_t)B_ * 128 * 6400;
    float* out2 = out1 + (size_t)B_ * 256 * 1600;

    k_cvt_w<<<168, 256>>>(w2[0], w2[1], w2[2]);
    k_sim<<<dim3(NCH, B_, 2), 224, sim_smem>>>(f2);
    k_reduce<<<380, 256>>>();
    k_softmax1<<<dim3(16, B_), 96>>>(w1, bn1[0], bn1[1], bn1[2], bn1[3]);
    k_resize2<<<500, 256>>>((float*)pr0, (float*)pr1);

    // heavy-first block order: level2 (8 chunks) -> level1 (4) -> level0 (2)
    AllP P;
    P.lv[0] = { f2, (const float*)simf, w2[2],
                bn2[2][0], bn2[2][1], bn2[2][2], bn2[2][3],
                WH + 81920, WL + 81920,
                out2, 512, 400, 4, 8, 0 };      // 4*8*4 = 128 blocks
    P.lv[1] = { f1, (const float*)pr1, w2[1],
                bn2[1][0], bn2[1][1], bn2[1][2], bn2[1][3],
                WH + 16384, WL + 16384,
                out1, 256, 1600, 13, 4, 128 };  // 13*4*4 = 208 blocks
    P.lv[2] = { f0, (const float*)pr0, w2[0],
                bn2[0][0], bn2[0][1], bn2[0][2], bn2[0][3],
                WH, WL,
                out0, 128, 6400, 50, 2, 336 };  // 50*2*4 = 400 blocks
    int total_blocks = 128 + 208 + 400;   // 736

    k_conv2t<<<total_blocks, 256, 52224>>>(P);
}

// round 9
// speedup vs baseline: 3.3925x; 1.0199x over previous
#include <cuda_runtime.h>
#include <cuda_bf16.h>
#include <cstdint>

// Sim2: temporal cost-volume + softmax + 1x1convs on a 3-level pyramid.
//   k_cvt_w    : fp32 -> split-bf16 planes of the [C][C] weight blocks
//   k_sim      : cost volume partials, f32x2 packed math, past-in-registers
//   k_reduce   : wide 16-chunk fold -> g_L (float2 granularity)
//   k_softmax1 : streaming two-pass softmax(81) + conv1 + BN + SiLU
//   k_conv2t   : unified 3-level C->C tensor-core GEMM; bilinear pr computed
//                in-prologue from g_simf; pr/BN/SiLU fp32 epilogue

#define B_    4
#define C2    512
#define HW2   400
#define NS_   81
#define NCH   16
#define WROWS 18
#define CROW  29

__device__ float g_Lpart[NCH * 12 * NS_ * HW2];
__device__ float g_L[12 * NS_ * HW2];
__device__ float g_simf[B_ * 4 * HW2];

// weights [o][k], k<C: lvl0 @0 (16384), lvl1 @16384 (65536), lvl2 @81920 (262144)
__device__ __align__(16) __nv_bfloat16 g_wh[344064];
__device__ __align__(16) __nv_bfloat16 g_wl[344064];

__device__ __forceinline__ void pack8(const float* v, uint4& hi, uint4& lo) {
    uint32_t h[4], l[4];
#pragma unroll
    for (int j = 0; j < 4; j++) {
        __nv_bfloat162 hh = __floats2bfloat162_rn(v[2*j], v[2*j+1]);
        float2 hf = __bfloat1622float2(hh);
        __nv_bfloat162 ll = __floats2bfloat162_rn(v[2*j] - hf.x, v[2*j+1] - hf.y);
        h[j] = *reinterpret_cast<uint32_t*>(&hh);
        l[j] = *reinterpret_cast<uint32_t*>(&ll);
    }
    hi = make_uint4(h[0], h[1], h[2], h[3]);
    lo = make_uint4(l[0], l[1], l[2], l[3]);
}

__device__ __forceinline__ unsigned long long addx2(unsigned long long a,
                                                    unsigned long long b) {
    unsigned long long r;
    asm("add.rn.f32x2 %0, %1, %2;" : "=l"(r) : "l"(a), "l"(b));
    return r;
}
__device__ __forceinline__ unsigned long long packx2(float lo, float hi) {
    unsigned long long r;
    asm("mov.b64 %0, {%1, %2};" : "=l"(r) : "f"(lo), "f"(hi));
    return r;
}

// ---------------------------------------------------------------------------
// Weight conversion: [C][C] blocks. 43008 items x 8. grid = 168 x 256.
// ---------------------------------------------------------------------------
__global__ __launch_bounds__(256) void k_cvt_w(
    const float* __restrict__ w0, const float* __restrict__ w1,
    const float* __restrict__ w2)
{
    int idx = blockIdx.x * 256 + threadIdx.x;
    if (idx >= 43008) return;
    const float* w; size_t dstOff; int C, e;
    if (idx < 2048)       { w = w0; dstOff = 0;     C = 128; e = idx * 8; }
    else if (idx < 10240) { w = w1; dstOff = 16384; C = 256; e = (idx - 2048) * 8; }
    else                  { w = w2; dstOff = 81920; C = 512; e = (idx - 10240) * 8; }
    int o = e / C, k = e - o * C;
    const float* s = w + (size_t)o * (C + 4) + k;
    float v[8];
#pragma unroll
    for (int j = 0; j < 8; j++) v[j] = s[j];
    uint4 hi, lo; pack8(v, hi, lo);
    *(uint4*)(g_wh + dstOff + e) = hi;
    *(uint4*)(g_wl + dstOff + e) = lo;
}

// ---------------------------------------------------------------------------
// Kernel: cost volume partials, f32x2 packed. grid = (NCH, B, 2), 224 thr.
// ---------------------------------------------------------------------------
__global__ __launch_bounds__(224) void k_sim(const float* __restrict__ f2)
{
    int cc = blockIdx.x;
    int b  = blockIdx.y;
    int h  = blockIdx.z;

    extern __shared__ unsigned long long curS2[];   // [16][WROWS*CROW]

    int tid = threadIdx.x;
    int r0  = h * 10;

    const float* curG = f2 + ((size_t)(b * 4 + 3) * C2 + cc * 32) * HW2;

    for (int i = tid; i < 16 * WROWS * 28; i += 224) {
        int c2  = i / (WROWS * 28);
        int rem = i - c2 * (WROWS * 28);
        int wr  = rem / 28, wc = rem - wr * 28;
        int gy  = r0 + wr - 4, gx = wc - 4;
        float lo = 0.f, hi = 0.f;
        if ((unsigned)gy < 20u && (unsigned)gx < 20u) {
            int g = gy * 20 + gx;
            lo = curG[(2 * c2) * HW2 + g];
            hi = curG[(2 * c2 + 1) * HW2 + g];
        }
        curS2[c2 * (WROWS * CROW) + wr * CROW + wc] = packx2(lo, hi);
    }
    __syncthreads();

    if (tid < 200) {
        unsigned long long np[3][16];
#pragma unroll
        for (int t = 0; t < 3; t++) {
            const float* pb = f2 + ((size_t)(b * 4 + t) * C2 + cc * 32) * HW2
                            + r0 * 20 + tid;
#pragma unroll
            for (int c2 = 0; c2 < 16; c2++)
                np[t][c2] = packx2(-pb[(2 * c2) * HW2], -pb[(2 * c2 + 1) * HW2]);
        }

        int lr  = tid / 20;
        int col = tid - lr * 20;
        size_t obase = (((size_t)cc * 12 + b * 3) * NS_) * HW2 + h * 200 + tid;
        const unsigned long long SGN = 0x8000000080000000ULL;

        for (int s = 0; s < NS_; s++) {
            int dy = s / 9, dx = s - dy * 9;
            const unsigned long long* cp =
                curS2 + (lr + dy) * CROW + col + dx;
            unsigned long long a0 = 0ULL, a1 = 0ULL, a2 = 0ULL;
#pragma unroll
            for (int c2 = 0; c2 < 16; c2++) {
                unsigned long long cv = cp[c2 * (WROWS * CROW)];
                unsigned long long d0 = addx2(cv, np[0][c2]);
                unsigned long long d1 = addx2(cv, np[1][c2]);
                unsigned long long d2 = addx2(cv, np[2][c2]);
                a0 = addx2(a0, d0 | SGN);
                a1 = addx2(a1, d1 | SGN);
                a2 = addx2(a2, d2 | SGN);
            }
            float r0f = __uint_as_float((unsigned)a0) + __uint_as_float((unsigned)(a0 >> 32));
            float r1f = __uint_as_float((unsigned)a1) + __uint_as_float((unsigned)(a1 >> 32));
            float r2f = __uint_as_float((unsigned)a2) + __uint_as_float((unsigned)(a2 >> 32));
            size_t o = obase + (size_t)s * HW2;
            g_Lpart[o]                         = r0f;
            g_Lpart[o + (size_t)NS_ * HW2]     = r1f;
            g_Lpart[o + (size_t)2 * NS_ * HW2] = r2f;
        }
    }
}

// ---------------------------------------------------------------------------
// Kernel: wide 16-chunk fold, float2 granularity. grid = 760 x 256.
// ---------------------------------------------------------------------------
__global__ __launch_bounds__(256) void k_reduce()
{
    int e = blockIdx.x * 256 + threadIdx.x;
    if (e >= 194400) return;
    const float2* src = (const float2*)g_Lpart + e;
    float2 a = src[0];
#pragma unroll
    for (int cc = 1; cc < NCH; cc++) {
        float2 v = src[(size_t)cc * 194400];
        a.x += v.x; a.y += v.y;
    }
    ((float2*)g_L)[e] = a;
}

// ---------------------------------------------------------------------------
// Kernel: streaming two-pass softmax(81) + conv1(243->4) + BN + SiLU.
// grid = (8, B), 192 threads = 3 t-groups x 64 lanes (50 px each).
// ---------------------------------------------------------------------------
__global__ __launch_bounds__(192) void k_softmax1(
    const float* __restrict__ w1,
    const float* __restrict__ g1, const float* __restrict__ b1,
    const float* __restrict__ m1, const float* __restrict__ v1)
{
    __shared__ float w1s[972];
    __shared__ float opart[12 * 64];

    int b    = blockIdx.y;
    int tid  = threadIdx.x;
    int t    = tid >> 6;
    int lane = tid & 63;
    int px   = blockIdx.x * 50 + lane;
    bool act = lane < 50;

    for (int i = tid; i < 972; i += 192) w1s[i] = w1[i];
    __syncthreads();

    if (act) {
        const float* Lb = g_L + ((size_t)(b * 3 + t) * NS_) * HW2 + px;
        float mx = -1e30f;
#pragma unroll
        for (int s = 0; s < NS_; s++)
            mx = fmaxf(mx, Lb[(size_t)s * HW2]);
        float Z = 0.f, u0 = 0.f, u1 = 0.f, u2 = 0.f, u3 = 0.f;
        const float* wt = w1s + t * 81;
#pragma unroll
        for (int s = 0; s < NS_; s++) {
            float e = __expf(Lb[(size_t)s * HW2] - mx);
            Z  += e;
            u0 += wt[s] * e;       u1 += wt[243 + s] * e;
            u2 += wt[486 + s] * e; u3 += wt[729 + s] * e;
        }
        float rz = 1.f / Z;
        opart[(t * 4 + 0) * 64 + lane] = u0 * rz;
        opart[(t * 4 + 1) * 64 + lane] = u1 * rz;
        opart[(t * 4 + 2) * 64 + lane] = u2 * rz;
        opart[(t * 4 + 3) * 64 + lane] = u3 * rz;
    }
    __syncthreads();

    if (t == 0 && act) {
#pragma unroll
        for (int oc = 0; oc < 4; oc++) {
            float o = opart[oc * 64 + lane] + opart[(4 + oc) * 64 + lane]
                    + opart[(8 + oc) * 64 + lane];
            float sc = g1[oc] * rsqrtf(v1[oc] + 1e-3f);
            float yv = (o - m1[oc]) * sc + b1[oc];
            g_simf[((size_t)b * 4 + oc) * HW2 + px] = yv / (1.f + __expf(-yv));
        }
    }
}

// ---------------------------------------------------------------------------
// Kernel: unified tensor-core conv2. BM=64 x BN=128, 256 threads, occ 2.
// pr tile computed in-prologue by bilinear from g_simf (identity at lvl2).
// smem: WH@0 WL@8K XH@16K XL@32K + prS@48K + wprS@50K = 51.2KB
// ---------------------------------------------------------------------------
struct LvP {
    const float* feat; const float* w;
    const float* gg; const float* bb; const float* mm; const float* vv;
    const __nv_bfloat16 *wh, *wl;
    float* out;
    int C, HW, Wo, nt, mt, blk0;
};
struct AllP { LvP lv[3]; };   // lv[0]=level2(heavy), lv[1]=level1, lv[2]=level0

__device__ __forceinline__ void ldsm4(uint32_t* r, uint32_t a) {
    asm volatile("ldmatrix.sync.aligned.m8n8.x4.shared.b16 {%0,%1,%2,%3},[%4];\n"
        : "=r"(r[0]), "=r"(r[1]), "=r"(r[2]), "=r"(r[3]) : "r"(a));
}
__device__ __forceinline__ void ldsm4t(uint32_t* r, uint32_t a) {
    asm volatile("ldmatrix.sync.aligned.m8n8.x4.trans.shared.b16 {%0,%1,%2,%3},[%4];\n"
        : "=r"(r[0]), "=r"(r[1]), "=r"(r[2]), "=r"(r[3]) : "r"(a));
}
__device__ __forceinline__ void mma16816(float* d, const uint32_t* a,
                                         uint32_t b0, uint32_t b1) {
    asm volatile("mma.sync.aligned.m16n8k16.row.col.f32.bf16.bf16.f32 "
        "{%0,%1,%2,%3},{%4,%5,%6,%7},{%8,%9},{%0,%1,%2,%3};\n"
        : "+f"(d[0]), "+f"(d[1]), "+f"(d[2]), "+f"(d[3])
        : "r"(a[0]), "r"(a[1]), "r"(a[2]), "r"(a[3]), "r"(b0), "r"(b1));
}

__global__ __launch_bounds__(256, 2) void k_conv2t(AllP P)
{
    extern __shared__ char smc[];
    const int OFF_WL = 8192, OFF_XH = 16384, OFF_XL = 32768;
    float* prS  = (float*)(smc + 49152);   // [4][128]
    float* wprS = (float*)(smc + 51200);   // [64][4]

    int bid = blockIdx.x;
    int li  = (bid >= P.lv[1].blk0) + (bid >= P.lv[2].blk0);
    LvP L = P.lv[li];

    int rb     = bid - L.blk0;
    int n_tile = rb % L.nt;
    int r2     = rb / L.nt;
    int m_tile = r2 % L.mt;
    int b      = r2 / L.mt;

    int ptile  = n_tile * 128;
    int K      = L.C + 4;
    int nchunk = L.C >> 6;

    int tid = threadIdx.x;
    int lane = tid & 31, wid = tid >> 5;
    int wm = wid >> 2, wn = wid & 3;

    uint32_t sb = (uint32_t)__cvta_generic_to_shared(smc);

    const float* xbase = L.feat + (size_t)(b * 4 + 3) * L.C * L.HW;
    const __nv_bfloat16* whb = L.wh + (size_t)m_tile * 64 * L.C;
    const __nv_bfloat16* wlb = L.wl + (size_t)m_tile * 64 * L.C;

    // pr tile: bilinear from g_simf (identity when Wo == 20)
    for (int i = tid; i < 512; i += 256) {
        int j = i >> 7, n = i & 127;
        int px = ptile + n;
        float v = 0.f;
        if (px < L.HW) {
            const float* sp = g_simf + (size_t)(b * 4 + j) * HW2;
            if (L.Wo == 20) {
                v = sp[px];
            } else {
                int yo = px / L.Wo, xo = px - yo * L.Wo;
                float s19 = 19.f / (float)(L.Wo - 1);
                float cy = yo * s19, cx = xo * s19;
                int y0 = (int)cy, x0 = (int)cx;
                int y1 = min(y0 + 1, 19), x1 = min(x0 + 1, 19);
                float wy = cy - (float)y0, wx = cx - (float)x0;
                v = (1.f - wy) * ((1.f - wx) * sp[y0 * 20 + x0] + wx * sp[y0 * 20 + x1])
                  +         wy * ((1.f - wx) * sp[y1 * 20 + x0] + wx * sp[y1 * 20 + x1]);
            }
        }
        prS[i] = v;
    }
    {
        int o = tid >> 2, jj = tid & 3;
        wprS[tid] = L.w[(size_t)(m_tile * 64 + o) * K + L.C + jj];
    }

    float acc[2][4][4];
#pragma unroll
    for (int i = 0; i < 2; i++)
#pragma unroll
        for (int j = 0; j < 4; j++)
#pragma unroll
            for (int q = 0; q < 4; q++) acc[i][j][q] = 0.f;

    for (int c = 0; c < nchunk; c++) {
        int kbase = c * 64;
#pragma unroll
        for (int it = 0; it < 2; it++) {
            int item = tid + it * 256;
            int o = item >> 3, u = item & 7;
            size_t si = (size_t)o * L.C + kbase + u * 8;
            int off = o * 128 + ((u ^ (o & 7)) << 4);
            *(uint4*)(smc + off)          = *(const uint4*)(whb + si);
            *(uint4*)(smc + OFF_WL + off) = *(const uint4*)(wlb + si);
        }
#pragma unroll
        for (int it = 0; it < 4; it++) {
            int item = tid + it * 256;
            int kl = item >> 4, u = item & 15;
            int px0 = ptile + u * 8;
            float v[8] = {0.f, 0.f, 0.f, 0.f, 0.f, 0.f, 0.f, 0.f};
            if (px0 < L.HW) {
                const float* src = xbase + (size_t)(kbase + kl) * L.HW + px0;
                *(float4*)v       = *(const float4*)src;
                *(float4*)(v + 4) = *(const float4*)(src + 4);
            }
            uint4 hi, lo; pack8(v, hi, lo);
            int off = kl * 256 + ((u ^ (kl & 7)) << 4);
            *(uint4*)(smc + OFF_XH + off) = hi;
            *(uint4*)(smc + OFF_XL + off) = lo;
        }
        __syncthreads();

#pragma unroll
        for (int ks = 0; ks < 4; ks++) {
            uint32_t ah[2][4], al[2][4];
#pragma unroll
            for (int mi = 0; mi < 2; mi++) {
                int rr = wm * 32 + mi * 16 + (lane & 15);
                int ku = ks * 2 + (lane >> 4);
                uint32_t a = sb + rr * 128 + ((ku ^ (rr & 7)) << 4);
                ldsm4(ah[mi], a);
                ldsm4(al[mi], a + OFF_WL);
            }
            uint32_t bh[2][4], bl[2][4];
#pragma unroll
            for (int g = 0; g < 2; g++) {
                int kr = ks * 16 + (lane & 15);
                int n0 = wn * 32 + g * 16 + ((lane >> 4) * 8);
                uint32_t a = sb + OFF_XH + kr * 256 + (((n0 >> 3) ^ (kr & 7)) << 4);
                ldsm4t(bh[g], a);
                ldsm4t(bl[g], a + (OFF_XL - OFF_XH));
            }
#pragma unroll
            for (int mi = 0; mi < 2; mi++)
#pragma unroll
                for (int g = 0; g < 2; g++)
#pragma unroll
                    for (int t = 0; t < 2; t++) {
                        int ni = g * 2 + t;
                        mma16816(acc[mi][ni], ah[mi], bh[g][2*t], bh[g][2*t + 1]);
                        mma16816(acc[mi][ni], ah[mi], bl[g][2*t], bl[g][2*t + 1]);
                        mma16816(acc[mi][ni], al[mi], bh[g][2*t], bh[g][2*t + 1]);
                    }
        }
        __syncthreads();
    }

    int ro = lane >> 2, co = (lane & 3) * 2;
#pragma unroll
    for (int mi = 0; mi < 2; mi++) {
#pragma unroll
        for (int half = 0; half < 2; half++) {
            int rloc = wm * 32 + mi * 16 + half * 8 + ro;
            int oo = m_tile * 64 + rloc;
            float w0 = wprS[rloc * 4 + 0], w1 = wprS[rloc * 4 + 1];
            float w2 = wprS[rloc * 4 + 2], w3 = wprS[rloc * 4 + 3];
            float sc = L.gg[oo] * rsqrtf(L.vv[oo] + 1e-3f);
            float sh = L.bb[oo] - L.mm[oo] * sc;
            float* ob = L.out + (size_t)(b * L.C + oo) * L.HW;
#pragma unroll
            for (int ni = 0; ni < 4; ni++) {
                int nloc = wn * 32 + ni * 8 + co;
                int px = ptile + nloc;
                if (px < L.HW) {
                    float p0 = acc[mi][ni][half * 2 + 0]
                             + w0 * prS[nloc]       + w1 * prS[128 + nloc]
                             + w2 * prS[256 + nloc] + w3 * prS[384 + nloc];
                    float p1 = acc[mi][ni][half * 2 + 1]
                             + w0 * prS[nloc + 1]       + w1 * prS[128 + nloc + 1]
                             + w2 * prS[256 + nloc + 1] + w3 * prS[384 + nloc + 1];
                    float y0 = p0 * sc + sh;
                    float y1 = p1 * sc + sh;
                    float2 r;
                    r.x = y0 / (1.f + __expf(-y0));
                    r.y = y1 / (1.f + __expf(-y1));
                    *(float2*)(ob + px) = r;
                }
            }
        }
    }
}

// ---------------------------------------------------------------------------
// Launch
// ---------------------------------------------------------------------------
extern "C" void kernel_launch(void* const* d_in, const int* in_sizes, int n_in,
                              void* d_out, int out_size)
{
    const float *f0 = nullptr, *f1 = nullptr, *f2 = nullptr, *w1 = nullptr;
    const float* bn1[4] = {nullptr, nullptr, nullptr, nullptr};
    const float* w2[3]  = {nullptr, nullptr, nullptr};
    const float* bn2[3][4];

    for (int i = 0; i < n_in; i++) {
        int sz = in_sizes[i];
        if (sz == 13107200)      f0 = (const float*)d_in[i];
        else if (sz == 6553600)  f1 = (const float*)d_in[i];
        else if (sz == 3276800)  f2 = (const float*)d_in[i];
        else if (sz == 972) {
            w1 = (const float*)d_in[i];
            for (int j = 0; j < 4; j++) bn1[j] = (const float*)d_in[i + 1 + j];
        } else if (sz == 16896) {
            w2[0] = (const float*)d_in[i];
            for (int j = 0; j < 4; j++) bn2[0][j] = (const float*)d_in[i + 1 + j];
        } else if (sz == 66560) {
            w2[1] = (const float*)d_in[i];
            for (int j = 0; j < 4; j++) bn2[1][j] = (const float*)d_in[i + 1 + j];
        } else if (sz == 264192) {
            w2[2] = (const float*)d_in[i];
            for (int j = 0; j < 4; j++) bn2[2][j] = (const float*)d_in[i + 1 + j];
        }
    }
    if (!f0 || !f1 || !f2 || !w1 || !w2[0] || !w2[1] || !w2[2]) return;

    int sim_smem = 16 * WROWS * CROW * 8;          // 66816 B
    cudaFuncSetAttribute(k_sim, cudaFuncAttributeMaxDynamicSharedMemorySize, sim_smem);
    cudaFuncSetAttribute(k_conv2t, cudaFuncAttributeMaxDynamicSharedMemorySize, 52224);

    void *wh, *wl;
    cudaGetSymbolAddress(&wh, g_wh);
    cudaGetSymbolAddress(&wl, g_wl);
    const __nv_bfloat16* WH = (const __nv_bfloat16*)wh;
    const __nv_bfloat16* WL = (const __nv_bfloat16*)wl;

    float* out0 = (float*)d_out;
    float* out1 = out0 + (size_t)B_ * 128 * 6400;
    float* out2 = out1 + (size_t)B_ * 256 * 1600;

    k_cvt_w<<<168, 256>>>(w2[0], w2[1], w2[2]);
    k_sim<<<dim3(NCH, B_, 2), 224, sim_smem>>>(f2);
    k_reduce<<<760, 256>>>();
    k_softmax1<<<dim3(8, B_), 192>>>(w1, bn1[0], bn1[1], bn1[2], bn1[3]);

    // heavy-first block order: level2 (8 chunks) -> level1 (4) -> level0 (2)
    AllP P;
    P.lv[0] = { f2, w2[2],
                bn2[2][0], bn2[2][1], bn2[2][2], bn2[2][3],
                WH + 81920, WL + 81920,
                out2, 512, 400, 20, 4, 8, 0 };      // 128 blocks
    P.lv[1] = { f1, w2[1],
                bn2[1][0], bn2[1][1], bn2[1][2], bn2[1][3],
                WH + 16384, WL + 16384,
                out1, 256, 1600, 40, 13, 4, 128 };  // 208 blocks
    P.lv[2] = { f0, w2[0],
                bn2[0][0], bn2[0][1], bn2[0][2], bn2[0][3],
                WH, WL,
                out0, 128, 6400, 80, 50, 2, 336 };  // 400 blocks
    int total_blocks = 128 + 208 + 400;   // 736

    k_conv2t<<<total_blocks, 256, 52224>>>(P);
}